// round 14
// baseline (speedup 1.0000x reference)
#include <cuda_runtime.h>
#include <cuda_pipeline.h>
#include <cuda_bf16.h>
#include <math.h>
#include <stdint.h>

#define Nn 2048
#define D0 256
#define D1 128
#define D2 32
#define Ff 416
#define NCLS 10
#define NL 4
#define SQRT3 1.7320508075688772f
#define NNsz ((size_t)Nn * Nn)

typedef unsigned long long u64;
typedef __nv_bfloat16 bf16;

__device__ __forceinline__ u64 pack2(float x) { u64 r; asm("mov.b64 %0, {%1, %1};" : "=l"(r) : "f"(x)); return r; }
__device__ __forceinline__ void fma2(u64& d, u64 a, u64 b) { asm("fma.rn.f32x2 %0, %1, %2, %0;" : "+l"(d) : "l"(a), "l"(b)); }
__device__ __forceinline__ float2 unpack2(u64 v) { float2 f; asm("mov.b64 {%0, %1}, %2;" : "=f"(f.x), "=f"(f.y) : "l"(v)); return f; }
__device__ __forceinline__ unsigned short bfu(float x) {
    bf16 b = __float2bfloat16_rn(x); return *(unsigned short*)&b;
}
__device__ __forceinline__ float bff(unsigned short u) {
    bf16 b = *(bf16*)&u; return __bfloat162float(b);
}
__device__ __forceinline__ void cvt2(float x, float y, uint32_t& hi, uint32_t& lo) {
    unsigned short h0 = bfu(x), h1 = bfu(y);
    unsigned short l0 = bfu(x - bff(h0)), l1 = bfu(y - bff(h1));
    hi = (uint32_t)h0 | ((uint32_t)h1 << 16);
    lo = (uint32_t)l0 | ((uint32_t)l1 << 16);
}
__device__ __forceinline__ void mma16(float c[4], const uint32_t a[4], const uint32_t b[2]) {
    asm volatile("mma.sync.aligned.m16n8k16.row.col.f32.bf16.bf16.f32 "
                 "{%0,%1,%2,%3}, {%4,%5,%6,%7}, {%8,%9}, {%0,%1,%2,%3};"
                 : "+f"(c[0]), "+f"(c[1]), "+f"(c[2]), "+f"(c[3])
                 : "r"(a[0]), "r"(a[1]), "r"(a[2]), "r"(a[3]), "r"(b[0]), "r"(b[1]));
}

// ---------------- device scratch ----------------
__device__ float g_x0[Nn * D0];
__device__ float g_x1[Nn * D1 * 3];
__device__ float g_x2[Nn * D2 * 5];
__device__ float g_inv[Nn * Ff];
__device__ float g_qk[Nn * 512];
__device__ bf16  g_attn[(size_t)4 * Nn * Nn];   // bf16 logits
__device__ bf16  g_attnb[(size_t)4 * Nn * Nn];  // bf16 probs
__device__ bf16  g_ab[NNsz];                    // bf16 head-mean
__device__ bf16  g_W[8 * NNsz];                 // bf16 a*Y class weights
__device__ bf16  g_Vt[1024 * Nn];               // rows: [v1 0..383|v2 384..543|v0 544..799|s1 800..927|s2 928..959]
__device__ float g_agg[Nn * 1088];
__device__ float g_ff[Nn * 512];
__device__ float g_gate[Nn * 160];
__device__ float g_qkpack[NL * 416 * 512];
__device__ float g_vpack[NL * 256 * 448];
__device__ float g_gpack[NL * 416 * 192];
__device__ float g_opack[256 * 64];

// ---------------- pack weights ----------------
__global__ void pack_kernel(const float* __restrict__ Wq, const float* __restrict__ Wk,
                            const float* __restrict__ Wv0, const float* __restrict__ Ws1,
                            const float* __restrict__ Ws2, const float* __restrict__ Wg,
                            const float* __restrict__ outW)
{
    const int R1 = NL * 416 * 512, R2 = NL * 256 * 448, R3 = NL * 416 * 192, R4 = 256 * 64;
    const int total = R1 + R2 + R3 + R4;
    for (int i = blockIdx.x * blockDim.x + threadIdx.x; i < total; i += gridDim.x * blockDim.x) {
        if (i < R1) {
            int l = i / (416 * 512), rem = i % (416 * 512), f = rem / 512, c = rem % 512;
            g_qkpack[i] = (c < 256) ? Wq[((size_t)l * 416 + f) * 256 + c] : Wk[((size_t)l * 416 + f) * 256 + (c - 256)];
        } else if (i < R1 + R2) {
            int j = i - R1, l = j / (256 * 448), rem = j % (256 * 448), d = rem / 448, c = rem % 448;
            float v = 0.f;
            if (c < 256)      v = Wv0[((size_t)l * 256 + d) * 256 + c];
            else if (c < 384) v = Ws1[((size_t)l * 256 + d) * 128 + (c - 256)];
            else if (c < 416) v = Ws2[((size_t)l * 256 + d) * 32 + (c - 384)];
            g_vpack[j] = v;
        } else if (i < R1 + R2 + R3) {
            int j = i - R1 - R2, l = j / (416 * 192), rem = j % (416 * 192), f = rem / 192, c = rem % 192;
            g_gpack[j] = (c < 160) ? Wg[((size_t)l * 416 + f) * 160 + c] : 0.f;
        } else {
            int j = i - R1 - R2 - R3, d = j / 64, c = j % 64;
            g_opack[j] = (c < 10) ? outW[d * 10 + c] : 0.f;
        }
    }
}

// ---------------- scalar epilogue helper ----------------
__device__ __forceinline__ void gemm_epi(float* C, const float* bias, int r, int c, int ldc,
                                         int act, int accum, int transC, float v)
{
    if (bias) v += bias[c];
    if (act == 1) v = v / (1.f + __expf(-v));
    else if (act == 2) v = 1.f / (1.f + __expf(-v));
    if (transC) ((bf16*)C)[(size_t)c * ldc + r] = __float2bfloat16_rn(v);
    else { size_t idx = (size_t)r * ldc + c; if (accum) C[idx] += v; else C[idx] = v; }
}

// ---------------- gemm_bf3: 64x64 tile, 3-pass split-bf16 mma node GEMM ----------------
// requires K%32==0; fp32 A[M,K](lda), B[K,N](ldb); near-fp32 accuracy.
__global__ __launch_bounds__(256)
void gemm_bf3(const float* __restrict__ A, const float* __restrict__ B,
              float* __restrict__ C, const float* __restrict__ bias,
              int Ncol, int K, int lda, int ldb, int ldc,
              int act, int accum, int transC)
{
    __shared__ float As[2][64][36];
    __shared__ float Bs[2][32][72];
    int tid = threadIdx.x, lane = tid & 31, wid = tid >> 5;
    int row0 = blockIdx.y * 64, col0 = blockIdx.x * 64;
    int g = lane >> 2, t = lane & 3;
    int wm = (wid >> 2) * 32, wn = (wid & 3) * 16;
    int nc = K >> 5;
    float c[2][2][4] = {};

#pragma unroll
    for (int i = 0; i < 2; i++) {
        int f2 = tid + i * 256, r = f2 >> 3, k4 = (f2 & 7) * 4;
        __pipeline_memcpy_async(&As[0][r][k4], &A[(size_t)(row0 + r) * lda + k4], 16);
    }
#pragma unroll
    for (int i = 0; i < 2; i++) {
        int f2 = tid + i * 256, k = f2 >> 4, c4 = (f2 & 15) * 4;
        __pipeline_memcpy_async(&Bs[0][k][c4], &B[(size_t)k * ldb + col0 + c4], 16);
    }
    __pipeline_commit();

    for (int ch = 0; ch < nc; ch++) {
        __pipeline_wait_prior(0);
        __syncthreads();
        if (ch + 1 < nc) {
            int s = (ch + 1) & 1, kk = (ch + 1) * 32;
#pragma unroll
            for (int i = 0; i < 2; i++) {
                int f2 = tid + i * 256, r = f2 >> 3, k4 = (f2 & 7) * 4;
                __pipeline_memcpy_async(&As[s][r][k4], &A[(size_t)(row0 + r) * lda + kk + k4], 16);
            }
#pragma unroll
            for (int i = 0; i < 2; i++) {
                int f2 = tid + i * 256, k = f2 >> 4, c4 = (f2 & 15) * 4;
                __pipeline_memcpy_async(&Bs[s][k][c4], &B[(size_t)(kk + k) * ldb + col0 + c4], 16);
            }
            __pipeline_commit();
        }
        int s = ch & 1;
#pragma unroll
        for (int k0 = 0; k0 < 32; k0 += 16) {
            int kb = k0 + 2 * t;
            uint32_t Ahi[2][4], Alo[2][4], Bhi[2][2], Blo[2][2];
#pragma unroll
            for (int mt = 0; mt < 2; mt++) {
                int r = wm + mt * 16 + g;
                float2 x0 = *(const float2*)&As[s][r][kb];
                float2 x1 = *(const float2*)&As[s][r + 8][kb];
                float2 x2 = *(const float2*)&As[s][r][kb + 8];
                float2 x3 = *(const float2*)&As[s][r + 8][kb + 8];
                cvt2(x0.x, x0.y, Ahi[mt][0], Alo[mt][0]);
                cvt2(x1.x, x1.y, Ahi[mt][1], Alo[mt][1]);
                cvt2(x2.x, x2.y, Ahi[mt][2], Alo[mt][2]);
                cvt2(x3.x, x3.y, Ahi[mt][3], Alo[mt][3]);
            }
#pragma unroll
            for (int nt = 0; nt < 2; nt++) {
                int rn = wn + nt * 8 + g;
                float b0 = Bs[s][kb][rn], b1 = Bs[s][kb + 1][rn];
                float b2 = Bs[s][kb + 8][rn], b3 = Bs[s][kb + 9][rn];
                cvt2(b0, b1, Bhi[nt][0], Blo[nt][0]);
                cvt2(b2, b3, Bhi[nt][1], Blo[nt][1]);
            }
#pragma unroll
            for (int mt = 0; mt < 2; mt++)
#pragma unroll
                for (int nt = 0; nt < 2; nt++) {
                    mma16(c[mt][nt], Ahi[mt], Bhi[nt]);
                    mma16(c[mt][nt], Alo[mt], Bhi[nt]);
                    mma16(c[mt][nt], Ahi[mt], Blo[nt]);
                }
        }
    }
#pragma unroll
    for (int mt = 0; mt < 2; mt++)
#pragma unroll
        for (int nt = 0; nt < 2; nt++) {
            int r0 = row0 + wm + mt * 16 + g;
            int cc = col0 + wn + nt * 8 + 2 * t;
#pragma unroll
            for (int half = 0; half < 2; half++) {
                int r = r0 + half * 8;
#pragma unroll
                for (int j = 0; j < 2; j++) {
                    int col = cc + j;
                    if (col < Ncol) gemm_epi(C, bias, r, col, ldc, act, accum, transC, c[mt][nt][half * 2 + j]);
                }
            }
        }
}

// ---------------- generic scalar GEMM (emb / out) ----------------
__global__ __launch_bounds__(256)
void gemm_f32(const float* __restrict__ A, const float* __restrict__ B,
              float* __restrict__ C, const float* __restrict__ bias,
              int M, int Ncol, int K, int lda, int ldb, int ldc,
              int act, int accum)
{
    __shared__ float As[64][36];
    __shared__ float Bs[32][72];
    int tid = threadIdx.x, tx = tid & 15, ty = tid >> 4;
    int row0 = blockIdx.y * 64, col0 = blockIdx.x * 64;
    int nc = (K + 31) >> 5;
    u64 acc2[4][2] = {};

    for (int c = 0; c < nc; c++) {
        __syncthreads();
        for (int i = tid; i < 64 * 32; i += 256) {
            int r = i >> 5, k = i & 31, kg = c * 32 + k;
            As[r][k] = (kg < K) ? A[(size_t)(row0 + r) * lda + kg] : 0.f;
        }
        for (int i = tid; i < 32 * 64; i += 256) {
            int k = i >> 6, cc = i & 63, kg = c * 32 + k;
            float v = 0.f;
            if (kg < K && col0 + cc < Ncol) v = B[(size_t)kg * ldb + col0 + cc];
            Bs[k][cc] = v;
        }
        __syncthreads();
#pragma unroll
        for (int k = 0; k < 32; k++) {
            u64 b0 = *(const u64*)&Bs[k][tx * 4];
            u64 b1 = *(const u64*)&Bs[k][tx * 4 + 2];
#pragma unroll
            for (int i = 0; i < 4; i++) {
                u64 a2 = pack2(As[ty * 4 + i][k]);
                fma2(acc2[i][0], a2, b0);
                fma2(acc2[i][1], a2, b1);
            }
        }
    }
#pragma unroll
    for (int i = 0; i < 4; i++) {
        int r = row0 + ty * 4 + i;
        float2 p0 = unpack2(acc2[i][0]), p1 = unpack2(acc2[i][1]);
        float va[4] = {p0.x, p0.y, p1.x, p1.y};
#pragma unroll
        for (int j = 0; j < 4; j++) {
            int c = col0 + tx * 4 + j;
            if (c < Ncol) gemm_epi(C, bias, r, c, ldc, act, accum, 0, va[j]);
        }
    }
}

// ---------------- 2-pass split-bf16 logits (hh + lo*h), bf16 out ----------------
#define LOG_LD 72
#define LOG_T (128 * LOG_LD * 2)
#define LOG_SMEM (3 * LOG_T)
__global__ __launch_bounds__(256)
void logits_mma_kernel(const float* __restrict__ qk)
{
    extern __shared__ char dsm[];
    unsigned short (*Qhi)[LOG_LD] = (unsigned short(*)[LOG_LD])(dsm);
    unsigned short (*Qlo)[LOG_LD] = (unsigned short(*)[LOG_LD])(dsm + LOG_T);
    unsigned short (*Khi)[LOG_LD] = (unsigned short(*)[LOG_LD])(dsm + 2 * LOG_T);
    int tid = threadIdx.x, lane = tid & 31, wid = tid >> 5;
    int m0 = blockIdx.x * 128, n0 = blockIdx.y * 128, h = blockIdx.z;

    for (int i = tid; i < 128 * 16; i += 256) {
        int r = i >> 4, k4 = (i & 15) * 4;
        float4 v = *(const float4*)&qk[(size_t)(n0 + r) * 512 + h * 64 + k4];
        ushort4 hs, ls;
        hs.x = bfu(v.x); ls.x = bfu(v.x - bff(hs.x));
        hs.y = bfu(v.y); ls.y = bfu(v.y - bff(hs.y));
        hs.z = bfu(v.z); ls.z = bfu(v.z - bff(hs.z));
        hs.w = bfu(v.w); ls.w = bfu(v.w - bff(hs.w));
        *(ushort4*)&Qhi[r][k4] = hs;
        *(ushort4*)&Qlo[r][k4] = ls;
        float4 w = *(const float4*)&qk[(size_t)(m0 + r) * 512 + 256 + h * 64 + k4];
        ushort4 ks;
        ks.x = bfu(w.x); ks.y = bfu(w.y); ks.z = bfu(w.z); ks.w = bfu(w.w);
        *(ushort4*)&Khi[r][k4] = ks;
    }
    __syncthreads();

    int g = lane >> 2, t = lane & 3;
    int wm = (wid >> 2) * 64, wn = (wid & 3) * 32;
    float c[4][4][4] = {};

#pragma unroll
    for (int k0 = 0; k0 < 64; k0 += 16) {
#pragma unroll
        for (int p = 0; p < 2; p++) {
            unsigned short (*A)[LOG_LD] = (p == 1) ? Qlo : Qhi;
            uint32_t a[4][4];
#pragma unroll
            for (int mt = 0; mt < 4; mt++) {
                int r = wm + mt * 16 + g;
                a[mt][0] = *(const uint32_t*)&A[r][k0 + 2 * t];
                a[mt][1] = *(const uint32_t*)&A[r + 8][k0 + 2 * t];
                a[mt][2] = *(const uint32_t*)&A[r][k0 + 2 * t + 8];
                a[mt][3] = *(const uint32_t*)&A[r + 8][k0 + 2 * t + 8];
            }
#pragma unroll
            for (int nt = 0; nt < 4; nt++) {
                int rn = wn + nt * 8 + g;
                uint32_t b[2] = {*(const uint32_t*)&Khi[rn][k0 + 2 * t],
                                 *(const uint32_t*)&Khi[rn][k0 + 2 * t + 8]};
#pragma unroll
                for (int mt = 0; mt < 4; mt++) mma16(c[mt][nt], a[mt], b);
            }
        }
    }
#pragma unroll
    for (int mt = 0; mt < 4; mt++)
#pragma unroll
        for (int nt = 0; nt < 4; nt++) {
            int row = n0 + wm + mt * 16 + g, col = m0 + wn + nt * 8 + 2 * t;
            size_t base = ((size_t)h * Nn + row) * Nn + col;
            uint32_t lo = (uint32_t)bfu(c[mt][nt][0] * 0.125f) | ((uint32_t)bfu(c[mt][nt][1] * 0.125f) << 16);
            uint32_t hi = (uint32_t)bfu(c[mt][nt][2] * 0.125f) | ((uint32_t)bfu(c[mt][nt][3] * 0.125f) << 16);
            *(uint32_t*)&g_attn[base] = lo;
            *(uint32_t*)&g_attn[base + 8 * (size_t)Nn] = hi;
        }
}

// ---------------- bf16 combined agg/mix/agg0 via mma.sync m16n8k16 ----------------
#define NN_LD 40
#define NN_ASZ (128 * NN_LD * 2)
#define NN_STG (2 * NN_ASZ)
#define NN_SMEM (2 * NN_STG)
__global__ __launch_bounds__(256)
void nn_mma_kernel()
{
    extern __shared__ char dsm[];
    int tid = threadIdx.x, lane = tid & 31, wid = tid >> 5;
    int ct = blockIdx.x, n0 = blockIdx.y * 128;

    const bf16* Ap; float* Cp; int NC, vtrow, col0, ldc, acc;
    if (ct < 4)       { NC = 128; Ap = g_ab; vtrow = ct * 128; col0 = ct * 128; Cp = g_agg; ldc = 1088; acc = 0; }
    else if (ct < 7)  { NC = 128; int c = ct - 4; Ap = g_W + (size_t)c * NNsz; vtrow = 800; col0 = 544 + c * 128; Cp = g_agg; ldc = 1088; acc = 0; }
    else if (ct == 7) { NC = 32;  Ap = g_ab; vtrow = 512; col0 = 512; Cp = g_agg; ldc = 1088; acc = 0; }
    else if (ct < 13) { NC = 32;  int c = ct - 8; Ap = g_W + (size_t)(3 + c) * NNsz; vtrow = 928; col0 = 928 + c * 32; Cp = g_agg; ldc = 1088; acc = 0; }
    else              { NC = 64;  int h = ct - 13; Ap = g_attnb + (size_t)h * NNsz; vtrow = 544 + h * 64; col0 = h * 64; Cp = g_x0; ldc = 256; acc = 1; }

    const bf16* Arow = Ap + (size_t)n0 * Nn;
    const bf16* Brow = g_Vt + (size_t)vtrow * Nn;
    int NT = NC / 32;
    int bcpy = NC * 4;

    int g = lane >> 2, t = lane & 3;
    int wm = (wid >> 2) * 64, wn = (wid & 3) * (NC / 4);
    float c[4][4][4] = {};

    const int NCH = Nn / 32;
    {
        unsigned short* As = (unsigned short*)(dsm);
        unsigned short* Bs = (unsigned short*)(dsm + NN_ASZ);
#pragma unroll
        for (int i = 0; i < 2; i++) {
            int idx = tid + i * 256, r = idx >> 2, c8 = (idx & 3) * 8;
            __pipeline_memcpy_async(&As[r * NN_LD + c8], &Arow[(size_t)r * Nn + c8], 16);
        }
#pragma unroll
        for (int i = 0; i < 2; i++) {
            int idx = tid + i * 256;
            if (idx < bcpy) {
                int r = idx >> 2, c8 = (idx & 3) * 8;
                __pipeline_memcpy_async(&Bs[r * NN_LD + c8], &Brow[(size_t)r * Nn + c8], 16);
            }
        }
        __pipeline_commit();
    }
#pragma unroll 1
    for (int ch = 0; ch < NCH; ch++) {
        __pipeline_wait_prior(0);
        __syncthreads();
        if (ch + 1 < NCH) {
            int s = (ch + 1) & 1, kk = (ch + 1) * 32;
            unsigned short* As = (unsigned short*)(dsm + s * NN_STG);
            unsigned short* Bs = (unsigned short*)(dsm + s * NN_STG + NN_ASZ);
#pragma unroll
            for (int i = 0; i < 2; i++) {
                int idx = tid + i * 256, r = idx >> 2, c8 = (idx & 3) * 8;
                __pipeline_memcpy_async(&As[r * NN_LD + c8], &Arow[(size_t)r * Nn + kk + c8], 16);
            }
#pragma unroll
            for (int i = 0; i < 2; i++) {
                int idx = tid + i * 256;
                if (idx < bcpy) {
                    int r = idx >> 2, c8 = (idx & 3) * 8;
                    __pipeline_memcpy_async(&Bs[r * NN_LD + c8], &Brow[(size_t)r * Nn + kk + c8], 16);
                }
            }
            __pipeline_commit();
        }
        const unsigned short* As = (const unsigned short*)(dsm + (ch & 1) * NN_STG);
        const unsigned short* Bs = (const unsigned short*)(dsm + (ch & 1) * NN_STG + NN_ASZ);
#pragma unroll
        for (int k0 = 0; k0 < 32; k0 += 16) {
            uint32_t a[4][4];
#pragma unroll
            for (int mt = 0; mt < 4; mt++) {
                int r = wm + mt * 16 + g;
                a[mt][0] = *(const uint32_t*)&As[r * NN_LD + k0 + 2 * t];
                a[mt][1] = *(const uint32_t*)&As[(r + 8) * NN_LD + k0 + 2 * t];
                a[mt][2] = *(const uint32_t*)&As[r * NN_LD + k0 + 2 * t + 8];
                a[mt][3] = *(const uint32_t*)&As[(r + 8) * NN_LD + k0 + 2 * t + 8];
            }
#pragma unroll
            for (int nt = 0; nt < 4; nt++) {
                if (nt < NT) {
                    int rn = wn + nt * 8 + g;
                    uint32_t b[2] = {*(const uint32_t*)&Bs[rn * NN_LD + k0 + 2 * t],
                                     *(const uint32_t*)&Bs[rn * NN_LD + k0 + 2 * t + 8]};
#pragma unroll
                    for (int mt = 0; mt < 4; mt++) mma16(c[mt][nt], a[mt], b);
                }
            }
        }
    }
#pragma unroll
    for (int mt = 0; mt < 4; mt++)
#pragma unroll
        for (int nt = 0; nt < 4; nt++) {
            if (nt < NT) {
                int row = n0 + wm + mt * 16 + g, col = col0 + wn + nt * 8 + 2 * t;
                size_t i0 = (size_t)row * ldc + col, i1 = (size_t)(row + 8) * ldc + col;
                if (acc) {
                    float2 o0 = *(float2*)&Cp[i0], o1 = *(float2*)&Cp[i1];
                    *(float2*)&Cp[i0] = make_float2(o0.x + c[mt][nt][0], o0.y + c[mt][nt][1]);
                    *(float2*)&Cp[i1] = make_float2(o1.x + c[mt][nt][2], o1.y + c[mt][nt][3]);
                } else {
                    *(float2*)&Cp[i0] = make_float2(c[mt][nt][0], c[mt][nt][1]);
                    *(float2*)&Cp[i1] = make_float2(c[mt][nt][2], c[mt][nt][3]);
                }
            }
        }
}

// ---------------- maxless softmax + fused build_w ----------------
__global__ __launch_bounds__(256)
void softmax_kernel(const float* __restrict__ pos)
{
    int n = blockIdx.x;
    __shared__ float row[Nn];
    __shared__ float accr[Nn];
    __shared__ float red[256];
    int tid = threadIdx.x;
    for (int i = tid * 4; i < Nn; i += 1024) *(float4*)&accr[i] = make_float4(0.f, 0.f, 0.f, 0.f);

    for (int h = 0; h < 4; h++) {
        const bf16* p = g_attn + ((size_t)h * Nn + n) * Nn;
        bf16* pb = g_attnb + ((size_t)h * Nn + n) * Nn;
        __syncthreads();
        float sum = 0.f;
        for (int i = tid * 4; i < Nn; i += 1024) {
            ushort4 u = *(const ushort4*)&p[i];
            float4 e = make_float4(__expf(bff(u.x)), __expf(bff(u.y)), __expf(bff(u.z)), __expf(bff(u.w)));
            *(float4*)&row[i] = e;
            sum += e.x + e.y + e.z + e.w;
        }
        red[tid] = sum; __syncthreads();
        for (int s = 128; s > 0; s >>= 1) { if (tid < s) red[tid] += red[tid + s]; __syncthreads(); }
        float inv = 1.f / red[0]; __syncthreads();
        for (int i = tid * 4; i < Nn; i += 1024) {
            float4 v = *(float4*)&row[i];
            float4 e = make_float4(v.x * inv, v.y * inv, v.z * inv, v.w * inv);
            ushort4 eb;
            eb.x = bfu(e.x); eb.y = bfu(e.y); eb.z = bfu(e.z); eb.w = bfu(e.w);
            *(ushort4*)&pb[i] = eb;
            float4 a = *(float4*)&accr[i];
            *(float4*)&accr[i] = make_float4(a.x + e.x, a.y + e.y, a.z + e.z, a.w + e.w);
        }
    }
    __syncthreads();
    float pnx = pos[n * 3 + 0], pny = pos[n * 3 + 1], pnz = pos[n * 3 + 2];
    for (int i = tid * 4; i < Nn; i += 1024) {
        float4 a4 = *(float4*)&accr[i];
        float av[4] = {a4.x * 0.25f, a4.y * 0.25f, a4.z * 0.25f, a4.w * 0.25f};
        ushort4 qb;
        qb.x = bfu(av[0]); qb.y = bfu(av[1]); qb.z = bfu(av[2]); qb.w = bfu(av[3]);
        *(ushort4*)&g_ab[(size_t)n * Nn + i] = qb;
        unsigned short o[8][4];
#pragma unroll
        for (int tt = 0; tt < 4; tt++) {
            int m = i + tt;
            float a = av[tt];
            float rx = pos[m * 3 + 0] - pnx;
            float ry = pos[m * 3 + 1] - pny;
            float rz = pos[m * 3 + 2] - pnz;
            float r2 = rx * rx + ry * ry + rz * rz;
            bool ok = r2 > 1e-12f;
            float inv = ok ? rsqrtf(r2) : 0.f;
            float valid = ok ? 1.f : 0.f;
            float ux = rx * inv, uy = ry * inv, uz = rz * inv;
            o[0][tt] = bfu(a * ux); o[1][tt] = bfu(a * uy); o[2][tt] = bfu(a * uz);
            o[3][tt] = bfu(a * (SQRT3 * ux * uy));
            o[4][tt] = bfu(a * (SQRT3 * uy * uz));
            o[5][tt] = bfu(a * (0.5f * (3.f * uz * uz - 1.f)) * valid);
            o[6][tt] = bfu(a * (SQRT3 * ux * uz));
            o[7][tt] = bfu(a * (0.5f * SQRT3 * (ux * ux - uy * uy)));
        }
#pragma unroll
        for (int cc = 0; cc < 8; cc++)
            *(ushort4*)&g_W[cc * NNsz + (size_t)n * Nn + i] = make_ushort4(o[cc][0], o[cc][1], o[cc][2], o[cc][3]);
    }
}

// ---------------- invariants (full; used pre-loop + post-finalize) ----------------
__global__ void invariants_kernel()
{
    const int total = Nn * Ff;
    for (int i = blockIdx.x * blockDim.x + threadIdx.x; i < total; i += gridDim.x * blockDim.x) {
        int n = i / Ff, c = i % Ff;
        float v;
        if (c < D0) v = g_x0[n * D0 + c];
        else if (c < D0 + D1) {
            const float* p = &g_x1[(n * D1 + (c - D0)) * 3];
            v = sqrtf(p[0] * p[0] + p[1] * p[1] + p[2] * p[2]);
        } else {
            const float* p = &g_x2[(n * D2 + (c - D0 - D1)) * 5];
            v = sqrtf(p[0] * p[0] + p[1] * p[1] + p[2] * p[2] + p[3] * p[3] + p[4] * p[4]);
        }
        g_inv[i] = v;
    }
}

// ---------------- v1/v2 channel mixes (transposed bf16 writes) ----------------
__global__ __launch_bounds__(128)
void v1_kernel(const float* __restrict__ Wv1)
{
    int m = blockIdx.x;
    __shared__ float sx[D1 * 3];
    int tid = threadIdx.x;
    for (int i = tid; i < D1 * 3; i += 128) sx[i] = g_x1[m * D1 * 3 + i];
    __syncthreads();
    float a0 = 0.f, a1 = 0.f, a2 = 0.f;
#pragma unroll 8
    for (int d = 0; d < D1; d++) {
        float w = Wv1[d * D1 + tid];
        a0 += sx[d * 3 + 0] * w;
        a1 += sx[d * 3 + 1] * w;
        a2 += sx[d * 3 + 2] * w;
    }
    g_Vt[(size_t)(tid * 3 + 0) * Nn + m] = __float2bfloat16_rn(a0);
    g_Vt[(size_t)(tid * 3 + 1) * Nn + m] = __float2bfloat16_rn(a1);
    g_Vt[(size_t)(tid * 3 + 2) * Nn + m] = __float2bfloat16_rn(a2);
}

__global__ __launch_bounds__(32)
void v2_kernel(const float* __restrict__ Wv2)
{
    int m = blockIdx.x;
    __shared__ float sx[D2 * 5];
    int tid = threadIdx.x;
    for (int i = tid; i < D2 * 5; i += 32) sx[i] = g_x2[m * D2 * 5 + i];
    __syncthreads();
    float a[5] = {};
#pragma unroll 8
    for (int d = 0; d < D2; d++) {
        float w = Wv2[d * D2 + tid];
#pragma unroll
        for (int c = 0; c < 5; c++) a[c] += sx[d * 5 + c] * w;
    }
#pragma unroll
    for (int c = 0; c < 5; c++) g_Vt[(size_t)(384 + tid * 5 + c) * Nn + m] = __float2bfloat16_rn(a[c]);
}

// ---------------- finalize ----------------
__global__ void finalize_kernel()
{
    const int total = Nn * 544;
    for (int i = blockIdx.x * blockDim.x + threadIdx.x; i < total; i += gridDim.x * blockDim.x) {
        int n = i / 544, t = i % 544;
        if (t < 384) {
            int d = t / 3, c = t % 3;
            g_x1[n * 384 + t] += g_agg[(size_t)n * 1088 + t] + g_agg[(size_t)n * 1088 + 544 + c * 128 + d];
        } else {
            int tt = t - 384, e = tt / 5, c = tt % 5;
            g_x2[n * 160 + tt] += g_agg[(size_t)n * 1088 + 384 + tt] + g_agg[(size_t)n * 1088 + 928 + c * 32 + e];
        }
    }
}

// ---------------- gate + fold into g_inv (g_inv norms *= gate) ----------------
__global__ void gate_inv_kernel()
{
    const int total = Nn * 704;   // 544 gate x1/x2 + 160 g_inv scale
    for (int i = blockIdx.x * blockDim.x + threadIdx.x; i < total; i += gridDim.x * blockDim.x) {
        int n = i / 704, t = i % 704;
        if (t < 384) g_x1[n * 384 + t] *= g_gate[n * 160 + t / 3];
        else if (t < 544) { int tt = t - 384; g_x2[n * 160 + tt] *= g_gate[n * 160 + 128 + tt / 5]; }
        else { int d = t - 544; g_inv[n * Ff + 256 + d] *= g_gate[n * 160 + d]; }
    }
}

__global__ void zero_kernel()
{
    const int t1 = Nn * 384, total = Nn * 384 + Nn * 160;
    for (int i = blockIdx.x * blockDim.x + threadIdx.x; i < total; i += gridDim.x * blockDim.x) {
        if (i < t1) g_x1[i] = 0.f; else g_x2[i - t1] = 0.f;
    }
}

// ---------------- host ----------------
extern "C" void kernel_launch(void* const* d_in, const int* in_sizes, int n_in,
                              void* d_out, int out_size)
{
    const float* x     = (const float*)d_in[0];
    const float* pos   = (const float*)d_in[1];
    const float* emb_W = (const float*)d_in[2];
    const float* emb_b = (const float*)d_in[3];
    const float* Wq    = (const float*)d_in[4];
    const float* Wk    = (const float*)d_in[5];
    const float* Wv0   = (const float*)d_in[6];
    const float* Wv1   = (const float*)d_in[7];
    const float* Wv2   = (const float*)d_in[8];
    const float* Ws1   = (const float*)d_in[9];
    const float* Ws2   = (const float*)d_in[10];
    const float* Wffa  = (const float*)d_in[11];
    const float* Wffb  = (const float*)d_in[12];
    const float* Wg    = (const float*)d_in[13];
    const float* out_W = (const float*)d_in[14];
    const float* out_b = (const float*)d_in[15];
    float* out = (float*)d_out;

    static int once = 0;
    if (!once) {
        cudaFuncSetAttribute(logits_mma_kernel, cudaFuncAttributeMaxDynamicSharedMemorySize, LOG_SMEM);
        cudaFuncSetAttribute(nn_mma_kernel, cudaFuncAttributeMaxDynamicSharedMemorySize, NN_SMEM);
        once = 1;
    }

    void* vp;
    cudaGetSymbolAddress(&vp, g_x0);     float* px0   = (float*)vp;
    cudaGetSymbolAddress(&vp, g_inv);    float* pinv  = (float*)vp;
    cudaGetSymbolAddress(&vp, g_qk);     float* pqk   = (float*)vp;
    cudaGetSymbolAddress(&vp, g_Vt);     bf16*  pVt   = (bf16*)vp;
    cudaGetSymbolAddress(&vp, g_ff);     float* pff   = (float*)vp;
    cudaGetSymbolAddress(&vp, g_gate);   float* pgate = (float*)vp;
    cudaGetSymbolAddress(&vp, g_qkpack); float* pqkp  = (float*)vp;
    cudaGetSymbolAddress(&vp, g_vpack);  float* pvp   = (float*)vp;
    cudaGetSymbolAddress(&vp, g_gpack);  float* pgp   = (float*)vp;
    cudaGetSymbolAddress(&vp, g_opack);  float* pop   = (float*)vp;

    pack_kernel<<<2048, 256>>>(Wq, Wk, Wv0, Ws1, Ws2, Wg, out_W);
    zero_kernel<<<512, 256>>>();
    gemm_f32<<<dim3(4, 32), 256>>>(x, emb_W, px0, emb_b, Nn, D0, 118, 118, D0, D0, 0, 0);
    invariants_kernel<<<1024, 256>>>();

    for (int l = 0; l < NL; l++) {
        const float* qk_l   = pqkp + (size_t)l * 416 * 512;
        const float* vp_l   = pvp  + (size_t)l * 256 * 448;
        const float* gp_l   = pgp  + (size_t)l * 416 * 192;
        const float* Wv1_l  = Wv1  + (size_t)l * D1 * D1;
        const float* Wv2_l  = Wv2  + (size_t)l * D2 * D2;
        const float* Wffa_l = Wffa + (size_t)l * D0 * 512;
        const float* Wffb_l = Wffb + (size_t)l * 512 * D0;

        gemm_bf3<<<dim3(8, 32), 256>>>(pinv, qk_l, pqk, nullptr, 512, Ff, Ff, 512, 512, 0, 0, 0);
        gemm_bf3<<<dim3(7, 32), 256>>>(px0, vp_l, (float*)(pVt + (size_t)544 * Nn), nullptr,
                                       448, D0, D0, 448, Nn, 0, 0, 1);
        v1_kernel<<<Nn, 128>>>(Wv1_l);
        v2_kernel<<<Nn, 32>>>(Wv2_l);

        logits_mma_kernel<<<dim3(16, 16, 4), 256, LOG_SMEM>>>(pqk);
        softmax_kernel<<<Nn, 256>>>(pos);

        nn_mma_kernel<<<dim3(17, 16), 256, NN_SMEM>>>();
        finalize_kernel<<<1024, 256>>>();

        gemm_bf3<<<dim3(8, 32), 256>>>(px0, Wffa_l, pff, nullptr, 512, D0, D0, 512, 512, 1, 0, 0);
        gemm_bf3<<<dim3(4, 32), 256>>>(pff, Wffb_l, px0, nullptr, D0, 512, 512, D0, D0, 0, 1, 0);

        invariants_kernel<<<1024, 256>>>();
        gemm_bf3<<<dim3(3, 32), 256>>>(pinv, gp_l, pgate, nullptr, 160, Ff, Ff, 192, 160, 2, 0, 0);
        gate_inv_kernel<<<1024, 256>>>();
    }
    gemm_f32<<<dim3(1, 32), 256>>>(px0, pop, out, out_b, Nn, NCLS, D0, D0, 64, NCLS, 0, 0);
}

// round 15
// speedup vs baseline: 1.0341x; 1.0341x over previous
#include <cuda_runtime.h>
#include <cuda_pipeline.h>
#include <cuda_bf16.h>
#include <math.h>
#include <stdint.h>

#define Nn 2048
#define D0 256
#define D1 128
#define D2 32
#define Ff 416
#define NCLS 10
#define NL 4
#define SQRT3 1.7320508075688772f
#define NNsz ((size_t)Nn * Nn)

typedef unsigned long long u64;
typedef __nv_bfloat16 bf16;

__device__ __forceinline__ u64 pack2(float x) { u64 r; asm("mov.b64 %0, {%1, %1};" : "=l"(r) : "f"(x)); return r; }
__device__ __forceinline__ void fma2(u64& d, u64 a, u64 b) { asm("fma.rn.f32x2 %0, %1, %2, %0;" : "+l"(d) : "l"(a), "l"(b)); }
__device__ __forceinline__ float2 unpack2(u64 v) { float2 f; asm("mov.b64 {%0, %1}, %2;" : "=f"(f.x), "=f"(f.y) : "l"(v)); return f; }
__device__ __forceinline__ unsigned short bfu(float x) {
    bf16 b = __float2bfloat16_rn(x); return *(unsigned short*)&b;
}
__device__ __forceinline__ float bff(unsigned short u) {
    bf16 b = *(bf16*)&u; return __bfloat162float(b);
}
__device__ __forceinline__ void mma16(float c[4], const uint32_t a[4], const uint32_t b[2]) {
    asm volatile("mma.sync.aligned.m16n8k16.row.col.f32.bf16.bf16.f32 "
                 "{%0,%1,%2,%3}, {%4,%5,%6,%7}, {%8,%9}, {%0,%1,%2,%3};"
                 : "+f"(c[0]), "+f"(c[1]), "+f"(c[2]), "+f"(c[3])
                 : "r"(a[0]), "r"(a[1]), "r"(a[2]), "r"(a[3]), "r"(b[0]), "r"(b[1]));
}

// ---------------- device scratch ----------------
__device__ float g_x0[Nn * D0];
__device__ float g_x1[Nn * D1 * 3];
__device__ float g_x2[Nn * D2 * 5];
__device__ float g_inv[Nn * Ff];
__device__ float g_qk[Nn * 512];
__device__ bf16  g_attn[(size_t)4 * Nn * Nn];   // bf16 logits
__device__ bf16  g_attnb[(size_t)4 * Nn * Nn];  // bf16 probs
__device__ bf16  g_ab[NNsz];                    // bf16 head-mean
__device__ bf16  g_W[8 * NNsz];                 // bf16 a*Y class weights
__device__ bf16  g_Vt[1024 * Nn];               // rows: [v1 0..383|v2 384..543|v0 544..799|s1 800..927|s2 928..959]
__device__ float g_agg[Nn * 1088];
__device__ float g_ff[Nn * 512];
__device__ float g_gate[Nn * 160];
__device__ float g_qkpack[NL * 416 * 512];
__device__ float g_vpack[NL * 256 * 448];
__device__ float g_gpack[NL * 416 * 192];
__device__ float g_opack[256 * 64];

// ---------------- pack weights ----------------
__global__ void pack_kernel(const float* __restrict__ Wq, const float* __restrict__ Wk,
                            const float* __restrict__ Wv0, const float* __restrict__ Ws1,
                            const float* __restrict__ Ws2, const float* __restrict__ Wg,
                            const float* __restrict__ outW)
{
    const int R1 = NL * 416 * 512, R2 = NL * 256 * 448, R3 = NL * 416 * 192, R4 = 256 * 64;
    const int total = R1 + R2 + R3 + R4;
    for (int i = blockIdx.x * blockDim.x + threadIdx.x; i < total; i += gridDim.x * blockDim.x) {
        if (i < R1) {
            int l = i / (416 * 512), rem = i % (416 * 512), f = rem / 512, c = rem % 512;
            g_qkpack[i] = (c < 256) ? Wq[((size_t)l * 416 + f) * 256 + c] : Wk[((size_t)l * 416 + f) * 256 + (c - 256)];
        } else if (i < R1 + R2) {
            int j = i - R1, l = j / (256 * 448), rem = j % (256 * 448), d = rem / 448, c = rem % 448;
            float v = 0.f;
            if (c < 256)      v = Wv0[((size_t)l * 256 + d) * 256 + c];
            else if (c < 384) v = Ws1[((size_t)l * 256 + d) * 128 + (c - 256)];
            else if (c < 416) v = Ws2[((size_t)l * 256 + d) * 32 + (c - 384)];
            g_vpack[j] = v;
        } else if (i < R1 + R2 + R3) {
            int j = i - R1 - R2, l = j / (416 * 192), rem = j % (416 * 192), f = rem / 192, c = rem % 192;
            g_gpack[j] = (c < 160) ? Wg[((size_t)l * 416 + f) * 160 + c] : 0.f;
        } else {
            int j = i - R1 - R2 - R3, d = j / 64, c = j % 64;
            g_opack[j] = (c < 10) ? outW[d * 10 + c] : 0.f;
        }
    }
}

// ---------------- scalar epilogue helper ----------------
__device__ __forceinline__ void gemm_epi(float* C, const float* bias, int r, int c, int ldc,
                                         int act, int accum, int transC, float v)
{
    if (bias) v += bias[c];
    if (act == 1) v = v / (1.f + __expf(-v));
    else if (act == 2) v = 1.f / (1.f + __expf(-v));
    if (transC) ((bf16*)C)[(size_t)c * ldc + r] = __float2bfloat16_rn(v);
    else { size_t idx = (size_t)r * ldc + c; if (accum) C[idx] += v; else C[idx] = v; }
}

// ---------------- gemm_bn32: 64x32 tile, 128 threads (layer node GEMMs) ----------------
// requires: K%32==0, Ncol%32==0, lda%4==0, ldb%4==0
__global__ __launch_bounds__(128)
void gemm_bn32(const float* __restrict__ A, const float* __restrict__ B,
               float* __restrict__ C, const float* __restrict__ bias,
               int K, int lda, int ldb, int ldc,
               int act, int accum, int transC)
{
    __shared__ float As[2][64][36];   // 36 floats = 144 B rows (16B-aligned for cp.async)
    __shared__ float Bs[2][32][36];
    int tid = threadIdx.x, tx = tid & 7, ty = tid >> 3;
    int row0 = blockIdx.y * 64, col0 = blockIdx.x * 32;
    int nc = K >> 5;
    u64 acc2[4][2] = {};

#pragma unroll
    for (int i = 0; i < 4; i++) {
        int idx = tid + i * 128, r = idx >> 3, k4 = (idx & 7) * 4;
        __pipeline_memcpy_async(&As[0][r][k4], &A[(size_t)(row0 + r) * lda + k4], 16);
    }
#pragma unroll
    for (int i = 0; i < 2; i++) {
        int idx = tid + i * 128, k = idx >> 3, c4 = (idx & 7) * 4;
        __pipeline_memcpy_async(&Bs[0][k][c4], &B[(size_t)k * ldb + col0 + c4], 16);
    }
    __pipeline_commit();
    for (int c = 0; c < nc; c++) {
        __pipeline_wait_prior(0);
        __syncthreads();
        if (c + 1 < nc) {
            int s = (c + 1) & 1, kk = (c + 1) * 32;
#pragma unroll
            for (int i = 0; i < 4; i++) {
                int idx = tid + i * 128, r = idx >> 3, k4 = (idx & 7) * 4;
                __pipeline_memcpy_async(&As[s][r][k4], &A[(size_t)(row0 + r) * lda + kk + k4], 16);
            }
#pragma unroll
            for (int i = 0; i < 2; i++) {
                int idx = tid + i * 128, k = idx >> 3, c4 = (idx & 7) * 4;
                __pipeline_memcpy_async(&Bs[s][k][c4], &B[(size_t)(kk + k) * ldb + col0 + c4], 16);
            }
            __pipeline_commit();
        }
        int s = c & 1;
#pragma unroll
        for (int k = 0; k < 32; k++) {
            u64 b0 = *(const u64*)&Bs[s][k][tx * 4];
            u64 b1 = *(const u64*)&Bs[s][k][tx * 4 + 2];
#pragma unroll
            for (int i = 0; i < 4; i++) {
                u64 a2 = pack2(As[s][ty * 4 + i][k]);
                fma2(acc2[i][0], a2, b0);
                fma2(acc2[i][1], a2, b1);
            }
        }
    }
#pragma unroll
    for (int i = 0; i < 4; i++) {
        int r = row0 + ty * 4 + i;
        float2 p0 = unpack2(acc2[i][0]), p1 = unpack2(acc2[i][1]);
        float va[4] = {p0.x, p0.y, p1.x, p1.y};
#pragma unroll
        for (int j = 0; j < 4; j++)
            gemm_epi(C, bias, r, col0 + tx * 4 + j, ldc, act, accum, transC, va[j]);
    }
}

// ---------------- generic scalar GEMM (emb / out) ----------------
__global__ __launch_bounds__(256)
void gemm_f32(const float* __restrict__ A, const float* __restrict__ B,
              float* __restrict__ C, const float* __restrict__ bias,
              int M, int Ncol, int K, int lda, int ldb, int ldc,
              int act, int accum)
{
    __shared__ float As[64][36];
    __shared__ float Bs[32][72];
    int tid = threadIdx.x, tx = tid & 15, ty = tid >> 4;
    int row0 = blockIdx.y * 64, col0 = blockIdx.x * 64;
    int nc = (K + 31) >> 5;
    u64 acc2[4][2] = {};

    for (int c = 0; c < nc; c++) {
        __syncthreads();
        for (int i = tid; i < 64 * 32; i += 256) {
            int r = i >> 5, k = i & 31, kg = c * 32 + k;
            As[r][k] = (kg < K) ? A[(size_t)(row0 + r) * lda + kg] : 0.f;
        }
        for (int i = tid; i < 32 * 64; i += 256) {
            int k = i >> 6, cc = i & 63, kg = c * 32 + k;
            float v = 0.f;
            if (kg < K && col0 + cc < Ncol) v = B[(size_t)kg * ldb + col0 + cc];
            Bs[k][cc] = v;
        }
        __syncthreads();
#pragma unroll
        for (int k = 0; k < 32; k++) {
            u64 b0 = *(const u64*)&Bs[k][tx * 4];
            u64 b1 = *(const u64*)&Bs[k][tx * 4 + 2];
#pragma unroll
            for (int i = 0; i < 4; i++) {
                u64 a2 = pack2(As[ty * 4 + i][k]);
                fma2(acc2[i][0], a2, b0);
                fma2(acc2[i][1], a2, b1);
            }
        }
    }
#pragma unroll
    for (int i = 0; i < 4; i++) {
        int r = row0 + ty * 4 + i;
        float2 p0 = unpack2(acc2[i][0]), p1 = unpack2(acc2[i][1]);
        float va[4] = {p0.x, p0.y, p1.x, p1.y};
#pragma unroll
        for (int j = 0; j < 4; j++) {
            int c = col0 + tx * 4 + j;
            if (c < Ncol) gemm_epi(C, bias, r, c, ldc, act, accum, 0, va[j]);
        }
    }
}

// ---------------- 2-pass split-bf16 logits (hh + lo*h), bf16 out ----------------
#define LOG_LD 72
#define LOG_T (128 * LOG_LD * 2)
#define LOG_SMEM (3 * LOG_T)
__global__ __launch_bounds__(256)
void logits_mma_kernel(const float* __restrict__ qk)
{
    extern __shared__ char dsm[];
    unsigned short (*Qhi)[LOG_LD] = (unsigned short(*)[LOG_LD])(dsm);
    unsigned short (*Qlo)[LOG_LD] = (unsigned short(*)[LOG_LD])(dsm + LOG_T);
    unsigned short (*Khi)[LOG_LD] = (unsigned short(*)[LOG_LD])(dsm + 2 * LOG_T);
    int tid = threadIdx.x, lane = tid & 31, wid = tid >> 5;
    int m0 = blockIdx.x * 128, n0 = blockIdx.y * 128, h = blockIdx.z;

    for (int i = tid; i < 128 * 16; i += 256) {
        int r = i >> 4, k4 = (i & 15) * 4;
        float4 v = *(const float4*)&qk[(size_t)(n0 + r) * 512 + h * 64 + k4];
        ushort4 hs, ls;
        hs.x = bfu(v.x); ls.x = bfu(v.x - bff(hs.x));
        hs.y = bfu(v.y); ls.y = bfu(v.y - bff(hs.y));
        hs.z = bfu(v.z); ls.z = bfu(v.z - bff(hs.z));
        hs.w = bfu(v.w); ls.w = bfu(v.w - bff(hs.w));
        *(ushort4*)&Qhi[r][k4] = hs;
        *(ushort4*)&Qlo[r][k4] = ls;
        float4 w = *(const float4*)&qk[(size_t)(m0 + r) * 512 + 256 + h * 64 + k4];
        ushort4 ks;
        ks.x = bfu(w.x); ks.y = bfu(w.y); ks.z = bfu(w.z); ks.w = bfu(w.w);
        *(ushort4*)&Khi[r][k4] = ks;
    }
    __syncthreads();

    int g = lane >> 2, t = lane & 3;
    int wm = (wid >> 2) * 64, wn = (wid & 3) * 32;
    float c[4][4][4] = {};

#pragma unroll
    for (int k0 = 0; k0 < 64; k0 += 16) {
#pragma unroll
        for (int p = 0; p < 2; p++) {
            unsigned short (*A)[LOG_LD] = (p == 1) ? Qlo : Qhi;
            uint32_t a[4][4];
#pragma unroll
            for (int mt = 0; mt < 4; mt++) {
                int r = wm + mt * 16 + g;
                a[mt][0] = *(const uint32_t*)&A[r][k0 + 2 * t];
                a[mt][1] = *(const uint32_t*)&A[r + 8][k0 + 2 * t];
                a[mt][2] = *(const uint32_t*)&A[r][k0 + 2 * t + 8];
                a[mt][3] = *(const uint32_t*)&A[r + 8][k0 + 2 * t + 8];
            }
#pragma unroll
            for (int nt = 0; nt < 4; nt++) {
                int rn = wn + nt * 8 + g;
                uint32_t b[2] = {*(const uint32_t*)&Khi[rn][k0 + 2 * t],
                                 *(const uint32_t*)&Khi[rn][k0 + 2 * t + 8]};
#pragma unroll
                for (int mt = 0; mt < 4; mt++) mma16(c[mt][nt], a[mt], b);
            }
        }
    }
#pragma unroll
    for (int mt = 0; mt < 4; mt++)
#pragma unroll
        for (int nt = 0; nt < 4; nt++) {
            int row = n0 + wm + mt * 16 + g, col = m0 + wn + nt * 8 + 2 * t;
            size_t base = ((size_t)h * Nn + row) * Nn + col;
            uint32_t lo = (uint32_t)bfu(c[mt][nt][0] * 0.125f) | ((uint32_t)bfu(c[mt][nt][1] * 0.125f) << 16);
            uint32_t hi = (uint32_t)bfu(c[mt][nt][2] * 0.125f) | ((uint32_t)bfu(c[mt][nt][3] * 0.125f) << 16);
            *(uint32_t*)&g_attn[base] = lo;
            *(uint32_t*)&g_attn[base + 8 * (size_t)Nn] = hi;
        }
}

// ---------------- bf16 combined agg/mix/agg0 via mma.sync m16n8k16 ----------------
#define NN_LD 40
#define NN_ASZ (128 * NN_LD * 2)
#define NN_STG (2 * NN_ASZ)
#define NN_SMEM (2 * NN_STG)
__global__ __launch_bounds__(256)
void nn_mma_kernel()
{
    extern __shared__ char dsm[];
    int tid = threadIdx.x, lane = tid & 31, wid = tid >> 5;
    int ct = blockIdx.x, n0 = blockIdx.y * 128;

    const bf16* Ap; float* Cp; int NC, vtrow, col0, ldc, acc;
    if (ct < 4)       { NC = 128; Ap = g_ab; vtrow = ct * 128; col0 = ct * 128; Cp = g_agg; ldc = 1088; acc = 0; }
    else if (ct < 7)  { NC = 128; int c = ct - 4; Ap = g_W + (size_t)c * NNsz; vtrow = 800; col0 = 544 + c * 128; Cp = g_agg; ldc = 1088; acc = 0; }
    else if (ct == 7) { NC = 32;  Ap = g_ab; vtrow = 512; col0 = 512; Cp = g_agg; ldc = 1088; acc = 0; }
    else if (ct < 13) { NC = 32;  int c = ct - 8; Ap = g_W + (size_t)(3 + c) * NNsz; vtrow = 928; col0 = 928 + c * 32; Cp = g_agg; ldc = 1088; acc = 0; }
    else              { NC = 64;  int h = ct - 13; Ap = g_attnb + (size_t)h * NNsz; vtrow = 544 + h * 64; col0 = h * 64; Cp = g_x0; ldc = 256; acc = 1; }

    const bf16* Arow = Ap + (size_t)n0 * Nn;
    const bf16* Brow = g_Vt + (size_t)vtrow * Nn;
    int NT = NC / 32;
    int bcpy = NC * 4;

    int g = lane >> 2, t = lane & 3;
    int wm = (wid >> 2) * 64, wn = (wid & 3) * (NC / 4);
    float c[4][4][4] = {};

    const int NCH = Nn / 32;
    {
        unsigned short* As = (unsigned short*)(dsm);
        unsigned short* Bs = (unsigned short*)(dsm + NN_ASZ);
#pragma unroll
        for (int i = 0; i < 2; i++) {
            int idx = tid + i * 256, r = idx >> 2, c8 = (idx & 3) * 8;
            __pipeline_memcpy_async(&As[r * NN_LD + c8], &Arow[(size_t)r * Nn + c8], 16);
        }
#pragma unroll
        for (int i = 0; i < 2; i++) {
            int idx = tid + i * 256;
            if (idx < bcpy) {
                int r = idx >> 2, c8 = (idx & 3) * 8;
                __pipeline_memcpy_async(&Bs[r * NN_LD + c8], &Brow[(size_t)r * Nn + c8], 16);
            }
        }
        __pipeline_commit();
    }
#pragma unroll 1
    for (int ch = 0; ch < NCH; ch++) {
        __pipeline_wait_prior(0);
        __syncthreads();
        if (ch + 1 < NCH) {
            int s = (ch + 1) & 1, kk = (ch + 1) * 32;
            unsigned short* As = (unsigned short*)(dsm + s * NN_STG);
            unsigned short* Bs = (unsigned short*)(dsm + s * NN_STG + NN_ASZ);
#pragma unroll
            for (int i = 0; i < 2; i++) {
                int idx = tid + i * 256, r = idx >> 2, c8 = (idx & 3) * 8;
                __pipeline_memcpy_async(&As[r * NN_LD + c8], &Arow[(size_t)r * Nn + kk + c8], 16);
            }
#pragma unroll
            for (int i = 0; i < 2; i++) {
                int idx = tid + i * 256;
                if (idx < bcpy) {
                    int r = idx >> 2, c8 = (idx & 3) * 8;
                    __pipeline_memcpy_async(&Bs[r * NN_LD + c8], &Brow[(size_t)r * Nn + kk + c8], 16);
                }
            }
            __pipeline_commit();
        }
        const unsigned short* As = (const unsigned short*)(dsm + (ch & 1) * NN_STG);
        const unsigned short* Bs = (const unsigned short*)(dsm + (ch & 1) * NN_STG + NN_ASZ);
#pragma unroll
        for (int k0 = 0; k0 < 32; k0 += 16) {
            uint32_t a[4][4];
#pragma unroll
            for (int mt = 0; mt < 4; mt++) {
                int r = wm + mt * 16 + g;
                a[mt][0] = *(const uint32_t*)&As[r * NN_LD + k0 + 2 * t];
                a[mt][1] = *(const uint32_t*)&As[(r + 8) * NN_LD + k0 + 2 * t];
                a[mt][2] = *(const uint32_t*)&As[r * NN_LD + k0 + 2 * t + 8];
                a[mt][3] = *(const uint32_t*)&As[(r + 8) * NN_LD + k0 + 2 * t + 8];
            }
#pragma unroll
            for (int nt = 0; nt < 4; nt++) {
                if (nt < NT) {
                    int rn = wn + nt * 8 + g;
                    uint32_t b[2] = {*(const uint32_t*)&Bs[rn * NN_LD + k0 + 2 * t],
                                     *(const uint32_t*)&Bs[rn * NN_LD + k0 + 2 * t + 8]};
#pragma unroll
                    for (int mt = 0; mt < 4; mt++) mma16(c[mt][nt], a[mt], b);
                }
            }
        }
    }
#pragma unroll
    for (int mt = 0; mt < 4; mt++)
#pragma unroll
        for (int nt = 0; nt < 4; nt++) {
            if (nt < NT) {
                int row = n0 + wm + mt * 16 + g, col = col0 + wn + nt * 8 + 2 * t;
                size_t i0 = (size_t)row * ldc + col, i1 = (size_t)(row + 8) * ldc + col;
                if (acc) {
                    float2 o0 = *(float2*)&Cp[i0], o1 = *(float2*)&Cp[i1];
                    *(float2*)&Cp[i0] = make_float2(o0.x + c[mt][nt][0], o0.y + c[mt][nt][1]);
                    *(float2*)&Cp[i1] = make_float2(o1.x + c[mt][nt][2], o1.y + c[mt][nt][3]);
                } else {
                    *(float2*)&Cp[i0] = make_float2(c[mt][nt][0], c[mt][nt][1]);
                    *(float2*)&Cp[i1] = make_float2(c[mt][nt][2], c[mt][nt][3]);
                }
            }
        }
}

// ---------------- maxless softmax + fused build_w ----------------
__global__ __launch_bounds__(256)
void softmax_kernel(const float* __restrict__ pos)
{
    int n = blockIdx.x;
    __shared__ float row[Nn];
    __shared__ float accr[Nn];
    __shared__ float red[256];
    int tid = threadIdx.x;
    for (int i = tid * 4; i < Nn; i += 1024) *(float4*)&accr[i] = make_float4(0.f, 0.f, 0.f, 0.f);

    for (int h = 0; h < 4; h++) {
        const bf16* p = g_attn + ((size_t)h * Nn + n) * Nn;
        bf16* pb = g_attnb + ((size_t)h * Nn + n) * Nn;
        __syncthreads();
        float sum = 0.f;
        for (int i = tid * 4; i < Nn; i += 1024) {
            ushort4 u = *(const ushort4*)&p[i];
            float4 e = make_float4(__expf(bff(u.x)), __expf(bff(u.y)), __expf(bff(u.z)), __expf(bff(u.w)));
            *(float4*)&row[i] = e;
            sum += e.x + e.y + e.z + e.w;
        }
        red[tid] = sum; __syncthreads();
        for (int s = 128; s > 0; s >>= 1) { if (tid < s) red[tid] += red[tid + s]; __syncthreads(); }
        float inv = 1.f / red[0]; __syncthreads();
        for (int i = tid * 4; i < Nn; i += 1024) {
            float4 v = *(float4*)&row[i];
            float4 e = make_float4(v.x * inv, v.y * inv, v.z * inv, v.w * inv);
            ushort4 eb;
            eb.x = bfu(e.x); eb.y = bfu(e.y); eb.z = bfu(e.z); eb.w = bfu(e.w);
            *(ushort4*)&pb[i] = eb;
            float4 a = *(float4*)&accr[i];
            *(float4*)&accr[i] = make_float4(a.x + e.x, a.y + e.y, a.z + e.z, a.w + e.w);
        }
    }
    __syncthreads();
    float pnx = pos[n * 3 + 0], pny = pos[n * 3 + 1], pnz = pos[n * 3 + 2];
    for (int i = tid * 4; i < Nn; i += 1024) {
        float4 a4 = *(float4*)&accr[i];
        float av[4] = {a4.x * 0.25f, a4.y * 0.25f, a4.z * 0.25f, a4.w * 0.25f};
        ushort4 qb;
        qb.x = bfu(av[0]); qb.y = bfu(av[1]); qb.z = bfu(av[2]); qb.w = bfu(av[3]);
        *(ushort4*)&g_ab[(size_t)n * Nn + i] = qb;
        unsigned short o[8][4];
#pragma unroll
        for (int tt = 0; tt < 4; tt++) {
            int m = i + tt;
            float a = av[tt];
            float rx = pos[m * 3 + 0] - pnx;
            float ry = pos[m * 3 + 1] - pny;
            float rz = pos[m * 3 + 2] - pnz;
            float r2 = rx * rx + ry * ry + rz * rz;
            bool ok = r2 > 1e-12f;
            float inv = ok ? rsqrtf(r2) : 0.f;
            float valid = ok ? 1.f : 0.f;
            float ux = rx * inv, uy = ry * inv, uz = rz * inv;
            o[0][tt] = bfu(a * ux); o[1][tt] = bfu(a * uy); o[2][tt] = bfu(a * uz);
            o[3][tt] = bfu(a * (SQRT3 * ux * uy));
            o[4][tt] = bfu(a * (SQRT3 * uy * uz));
            o[5][tt] = bfu(a * (0.5f * (3.f * uz * uz - 1.f)) * valid);
            o[6][tt] = bfu(a * (SQRT3 * ux * uz));
            o[7][tt] = bfu(a * (0.5f * SQRT3 * (ux * ux - uy * uy)));
        }
#pragma unroll
        for (int cc = 0; cc < 8; cc++)
            *(ushort4*)&g_W[cc * NNsz + (size_t)n * Nn + i] = make_ushort4(o[cc][0], o[cc][1], o[cc][2], o[cc][3]);
    }
}

// ---------------- invariants (pre-loop + post-ff) ----------------
__global__ void invariants_kernel()
{
    const int total = Nn * Ff;
    for (int i = blockIdx.x * blockDim.x + threadIdx.x; i < total; i += gridDim.x * blockDim.x) {
        int n = i / Ff, c = i % Ff;
        float v;
        if (c < D0) v = g_x0[n * D0 + c];
        else if (c < D0 + D1) {
            const float* p = &g_x1[(n * D1 + (c - D0)) * 3];
            v = sqrtf(p[0] * p[0] + p[1] * p[1] + p[2] * p[2]);
        } else {
            const float* p = &g_x2[(n * D2 + (c - D0 - D1)) * 5];
            v = sqrtf(p[0] * p[0] + p[1] * p[1] + p[2] * p[2] + p[3] * p[3] + p[4] * p[4]);
        }
        g_inv[i] = v;
    }
}

// ---------------- v1/v2 channel mixes (transposed bf16 writes) ----------------
__global__ __launch_bounds__(128)
void v1_kernel(const float* __restrict__ Wv1)
{
    int m = blockIdx.x;
    __shared__ float sx[D1 * 3];
    int tid = threadIdx.x;
    for (int i = tid; i < D1 * 3; i += 128) sx[i] = g_x1[m * D1 * 3 + i];
    __syncthreads();
    float a0 = 0.f, a1 = 0.f, a2 = 0.f;
#pragma unroll 8
    for (int d = 0; d < D1; d++) {
        float w = Wv1[d * D1 + tid];
        a0 += sx[d * 3 + 0] * w;
        a1 += sx[d * 3 + 1] * w;
        a2 += sx[d * 3 + 2] * w;
    }
    g_Vt[(size_t)(tid * 3 + 0) * Nn + m] = __float2bfloat16_rn(a0);
    g_Vt[(size_t)(tid * 3 + 1) * Nn + m] = __float2bfloat16_rn(a1);
    g_Vt[(size_t)(tid * 3 + 2) * Nn + m] = __float2bfloat16_rn(a2);
}

__global__ __launch_bounds__(32)
void v2_kernel(const float* __restrict__ Wv2)
{
    int m = blockIdx.x;
    __shared__ float sx[D2 * 5];
    int tid = threadIdx.x;
    for (int i = tid; i < D2 * 5; i += 32) sx[i] = g_x2[m * D2 * 5 + i];
    __syncthreads();
    float a[5] = {};
#pragma unroll 8
    for (int d = 0; d < D2; d++) {
        float w = Wv2[d * D2 + tid];
#pragma unroll
        for (int c = 0; c < 5; c++) a[c] += sx[d * 5 + c] * w;
    }
#pragma unroll
    for (int c = 0; c < 5; c++) g_Vt[(size_t)(384 + tid * 5 + c) * Nn + m] = __float2bfloat16_rn(a[c]);
}

// ---------------- finalize ----------------
__global__ void finalize_kernel()
{
    const int total = Nn * 544;
    for (int i = blockIdx.x * blockDim.x + threadIdx.x; i < total; i += gridDim.x * blockDim.x) {
        int n = i / 544, t = i % 544;
        if (t < 384) {
            int d = t / 3, c = t % 3;
            g_x1[n * 384 + t] += g_agg[(size_t)n * 1088 + t] + g_agg[(size_t)n * 1088 + 544 + c * 128 + d];
        } else {
            int tt = t - 384, e = tt / 5, c = tt % 5;
            g_x2[n * 160 + tt] += g_agg[(size_t)n * 1088 + 384 + tt] + g_agg[(size_t)n * 1088 + 928 + c * 32 + e];
        }
    }
}

// ---------------- gate + fold into g_inv ----------------
__global__ void gate_inv_kernel()
{
    const int total = Nn * 704;
    for (int i = blockIdx.x * blockDim.x + threadIdx.x; i < total; i += gridDim.x * blockDim.x) {
        int n = i / 704, t = i % 704;
        if (t < 384) g_x1[n * 384 + t] *= g_gate[n * 160 + t / 3];
        else if (t < 544) { int tt = t - 384; g_x2[n * 160 + tt] *= g_gate[n * 160 + 128 + tt / 5]; }
        else { int d = t - 544; g_inv[n * Ff + 256 + d] *= g_gate[n * 160 + d]; }
    }
}

__global__ void zero_kernel()
{
    const int t1 = Nn * 384, total = Nn * 384 + Nn * 160;
    for (int i = blockIdx.x * blockDim.x + threadIdx.x; i < total; i += gridDim.x * blockDim.x) {
        if (i < t1) g_x1[i] = 0.f; else g_x2[i - t1] = 0.f;
    }
}

// ---------------- host ----------------
extern "C" void kernel_launch(void* const* d_in, const int* in_sizes, int n_in,
                              void* d_out, int out_size)
{
    const float* x     = (const float*)d_in[0];
    const float* pos   = (const float*)d_in[1];
    const float* emb_W = (const float*)d_in[2];
    const float* emb_b = (const float*)d_in[3];
    const float* Wq    = (const float*)d_in[4];
    const float* Wk    = (const float*)d_in[5];
    const float* Wv0   = (const float*)d_in[6];
    const float* Wv1   = (const float*)d_in[7];
    const float* Wv2   = (const float*)d_in[8];
    const float* Ws1   = (const float*)d_in[9];
    const float* Ws2   = (const float*)d_in[10];
    const float* Wffa  = (const float*)d_in[11];
    const float* Wffb  = (const float*)d_in[12];
    const float* Wg    = (const float*)d_in[13];
    const float* out_W = (const float*)d_in[14];
    const float* out_b = (const float*)d_in[15];
    float* out = (float*)d_out;

    static int once = 0;
    if (!once) {
        cudaFuncSetAttribute(logits_mma_kernel, cudaFuncAttributeMaxDynamicSharedMemorySize, LOG_SMEM);
        cudaFuncSetAttribute(nn_mma_kernel, cudaFuncAttributeMaxDynamicSharedMemorySize, NN_SMEM);
        once = 1;
    }

    void* vp;
    cudaGetSymbolAddress(&vp, g_x0);     float* px0   = (float*)vp;
    cudaGetSymbolAddress(&vp, g_inv);    float* pinv  = (float*)vp;
    cudaGetSymbolAddress(&vp, g_qk);     float* pqk   = (float*)vp;
    cudaGetSymbolAddress(&vp, g_Vt);     bf16*  pVt   = (bf16*)vp;
    cudaGetSymbolAddress(&vp, g_ff);     float* pff   = (float*)vp;
    cudaGetSymbolAddress(&vp, g_gate);   float* pgate = (float*)vp;
    cudaGetSymbolAddress(&vp, g_qkpack); float* pqkp  = (float*)vp;
    cudaGetSymbolAddress(&vp, g_vpack);  float* pvp   = (float*)vp;
    cudaGetSymbolAddress(&vp, g_gpack);  float* pgp   = (float*)vp;
    cudaGetSymbolAddress(&vp, g_opack);  float* pop   = (float*)vp;

    pack_kernel<<<2048, 256>>>(Wq, Wk, Wv0, Ws1, Ws2, Wg, out_W);
    zero_kernel<<<512, 256>>>();
    gemm_f32<<<dim3(4, 32), 256>>>(x, emb_W, px0, emb_b, Nn, D0, 118, 118, D0, D0, 0, 0);
    invariants_kernel<<<1024, 256>>>();

    for (int l = 0; l < NL; l++) {
        const float* qk_l   = pqkp + (size_t)l * 416 * 512;
        const float* vp_l   = pvp  + (size_t)l * 256 * 448;
        const float* gp_l   = pgp  + (size_t)l * 416 * 192;
        const float* Wv1_l  = Wv1  + (size_t)l * D1 * D1;
        const float* Wv2_l  = Wv2  + (size_t)l * D2 * D2;
        const float* Wffa_l = Wffa + (size_t)l * D0 * 512;
        const float* Wffb_l = Wffb + (size_t)l * 512 * D0;

        gemm_bn32<<<dim3(16, 32), 128>>>(pinv, qk_l, pqk, nullptr, Ff, Ff, 512, 512, 0, 0, 0);
        gemm_bn32<<<dim3(13, 32), 128>>>(px0, vp_l, (float*)(pVt + (size_t)544 * Nn), nullptr,
                                         D0, D0, 448, Nn, 0, 0, 1);
        v1_kernel<<<Nn, 128>>>(Wv1_l);
        v2_kernel<<<Nn, 32>>>(Wv2_l);

        logits_mma_kernel<<<dim3(16, 16, 4), 256, LOG_SMEM>>>(pqk);
        softmax_kernel<<<Nn, 256>>>(pos);

        nn_mma_kernel<<<dim3(17, 16), 256, NN_SMEM>>>();
        finalize_kernel<<<1024, 256>>>();

        gemm_bn32<<<dim3(16, 32), 128>>>(px0, Wffa_l, pff, nullptr, D0, D0, 512, 512, 1, 0, 0);
        gemm_bn32<<<dim3(8, 32), 128>>>(pff, Wffb_l, px0, nullptr, 512, 512, D0, D0, 0, 1, 0);

        invariants_kernel<<<1024, 256>>>();
        gemm_bn32<<<dim3(5, 32), 128>>>(pinv, gp_l, pgate, nullptr, Ff, Ff, 192, 160, 2, 0, 0);
        gate_inv_kernel<<<1024, 256>>>();
    }
    gemm_f32<<<dim3(1, 32), 256>>>(px0, pop, out, out_b, Nn, NCLS, D0, D0, 64, NCLS, 0, 0);
}

// round 16
// speedup vs baseline: 1.1475x; 1.1096x over previous
#include <cuda_runtime.h>
#include <cuda_pipeline.h>
#include <cuda_bf16.h>
#include <math.h>
#include <stdint.h>

#define Nn 2048
#define D0 256
#define D1 128
#define D2 32
#define Ff 416
#define NCLS 10
#define NL 4
#define SQRT3 1.7320508075688772f
#define NNsz ((size_t)Nn * Nn)

typedef unsigned long long u64;
typedef __nv_bfloat16 bf16;

__device__ __forceinline__ u64 pack2(float x) { u64 r; asm("mov.b64 %0, {%1, %1};" : "=l"(r) : "f"(x)); return r; }
__device__ __forceinline__ void fma2(u64& d, u64 a, u64 b) { asm("fma.rn.f32x2 %0, %1, %2, %0;" : "+l"(d) : "l"(a), "l"(b)); }
__device__ __forceinline__ float2 unpack2(u64 v) { float2 f; asm("mov.b64 {%0, %1}, %2;" : "=f"(f.x), "=f"(f.y) : "l"(v)); return f; }
__device__ __forceinline__ unsigned short bfu(float x) {
    bf16 b = __float2bfloat16_rn(x); return *(unsigned short*)&b;
}
__device__ __forceinline__ float bff(unsigned short u) {
    bf16 b = *(bf16*)&u; return __bfloat162float(b);
}
__device__ __forceinline__ void mma16(float c[4], const uint32_t a[4], const uint32_t b[2]) {
    asm volatile("mma.sync.aligned.m16n8k16.row.col.f32.bf16.bf16.f32 "
                 "{%0,%1,%2,%3}, {%4,%5,%6,%7}, {%8,%9}, {%0,%1,%2,%3};"
                 : "+f"(c[0]), "+f"(c[1]), "+f"(c[2]), "+f"(c[3])
                 : "r"(a[0]), "r"(a[1]), "r"(a[2]), "r"(a[3]), "r"(b[0]), "r"(b[1]));
}

// ---------------- device scratch ----------------
__device__ float g_x0[Nn * D0];
__device__ float g_x1[Nn * D1 * 3];
__device__ float g_x2[Nn * D2 * 5];
__device__ float g_inv[Nn * Ff];
__device__ float g_qk[Nn * 512];
__device__ bf16  g_attn[(size_t)4 * Nn * Nn];
__device__ bf16  g_attnb[(size_t)4 * Nn * Nn];
__device__ bf16  g_ab[NNsz];
__device__ bf16  g_W[8 * NNsz];
__device__ bf16  g_Vt[1024 * Nn];   // [v1 0..383|v2 384..543|v0 544..799|s1 800..927|s2 928..959]
__device__ float g_agg[Nn * 1088];
__device__ float g_ff[Nn * 512];
__device__ float g_gate[Nn * 160];
__device__ float g_qkpack[NL * 416 * 512];
__device__ float g_vpack[NL * 256 * 448];
__device__ float g_gpack[NL * 416 * 192];
__device__ float g_opack[256 * 64];

// ---------------- pack weights ----------------
__global__ void pack_kernel(const float* __restrict__ Wq, const float* __restrict__ Wk,
                            const float* __restrict__ Wv0, const float* __restrict__ Ws1,
                            const float* __restrict__ Ws2, const float* __restrict__ Wg,
                            const float* __restrict__ outW)
{
    const int R1 = NL * 416 * 512, R2 = NL * 256 * 448, R3 = NL * 416 * 192, R4 = 256 * 64;
    const int total = R1 + R2 + R3 + R4;
    for (int i = blockIdx.x * blockDim.x + threadIdx.x; i < total; i += gridDim.x * blockDim.x) {
        if (i < R1) {
            int l = i / (416 * 512), rem = i % (416 * 512), f = rem / 512, c = rem % 512;
            g_qkpack[i] = (c < 256) ? Wq[((size_t)l * 416 + f) * 256 + c] : Wk[((size_t)l * 416 + f) * 256 + (c - 256)];
        } else if (i < R1 + R2) {
            int j = i - R1, l = j / (256 * 448), rem = j % (256 * 448), d = rem / 448, c = rem % 448;
            float v = 0.f;
            if (c < 256)      v = Wv0[((size_t)l * 256 + d) * 256 + c];
            else if (c < 384) v = Ws1[((size_t)l * 256 + d) * 128 + (c - 256)];
            else if (c < 416) v = Ws2[((size_t)l * 256 + d) * 32 + (c - 384)];
            g_vpack[j] = v;
        } else if (i < R1 + R2 + R3) {
            int j = i - R1 - R2, l = j / (416 * 192), rem = j % (416 * 192), f = rem / 192, c = rem % 192;
            g_gpack[j] = (c < 160) ? Wg[((size_t)l * 416 + f) * 160 + c] : 0.f;
        } else {
            int j = i - R1 - R2 - R3, d = j / 64, c = j % 64;
            g_opack[j] = (c < 10) ? outW[d * 10 + c] : 0.f;
        }
    }
}

// ---------------- scalar epilogue helper ----------------
__device__ __forceinline__ void gemm_epi(float* C, const float* bias, int r, int c, int ldc,
                                         int act, int accum, int transC, float v)
{
    if (bias) v += bias[c];
    if (act == 1) v = v / (1.f + __expf(-v));
    else if (act == 2) v = 1.f / (1.f + __expf(-v));
    if (transC) ((bf16*)C)[(size_t)c * ldc + r] = __float2bfloat16_rn(v);
    else { size_t idx = (size_t)r * ldc + c; if (accum) C[idx] += v; else C[idx] = v; }
}

// ---------------- gemm_bn32: 64x32 tile, 128 threads ----------------
__global__ __launch_bounds__(128)
void gemm_bn32(const float* __restrict__ A, const float* __restrict__ B,
               float* __restrict__ C, const float* __restrict__ bias,
               int K, int lda, int ldb, int ldc,
               int act, int accum, int transC)
{
    __shared__ float As[2][64][36];
    __shared__ float Bs[2][32][36];
    int tid = threadIdx.x, tx = tid & 7, ty = tid >> 3;
    int row0 = blockIdx.y * 64, col0 = blockIdx.x * 32;
    int nc = K >> 5;
    u64 acc2[4][2] = {};

#pragma unroll
    for (int i = 0; i < 4; i++) {
        int idx = tid + i * 128, r = idx >> 3, k4 = (idx & 7) * 4;
        __pipeline_memcpy_async(&As[0][r][k4], &A[(size_t)(row0 + r) * lda + k4], 16);
    }
#pragma unroll
    for (int i = 0; i < 2; i++) {
        int idx = tid + i * 128, k = idx >> 3, c4 = (idx & 7) * 4;
        __pipeline_memcpy_async(&Bs[0][k][c4], &B[(size_t)k * ldb + col0 + c4], 16);
    }
    __pipeline_commit();
    for (int c = 0; c < nc; c++) {
        __pipeline_wait_prior(0);
        __syncthreads();
        if (c + 1 < nc) {
            int s = (c + 1) & 1, kk = (c + 1) * 32;
#pragma unroll
            for (int i = 0; i < 4; i++) {
                int idx = tid + i * 128, r = idx >> 3, k4 = (idx & 7) * 4;
                __pipeline_memcpy_async(&As[s][r][k4], &A[(size_t)(row0 + r) * lda + kk + k4], 16);
            }
#pragma unroll
            for (int i = 0; i < 2; i++) {
                int idx = tid + i * 128, k = idx >> 3, c4 = (idx & 7) * 4;
                __pipeline_memcpy_async(&Bs[s][k][c4], &B[(size_t)(kk + k) * ldb + col0 + c4], 16);
            }
            __pipeline_commit();
        }
        int s = c & 1;
#pragma unroll
        for (int k = 0; k < 32; k++) {
            u64 b0 = *(const u64*)&Bs[s][k][tx * 4];
            u64 b1 = *(const u64*)&Bs[s][k][tx * 4 + 2];
#pragma unroll
            for (int i = 0; i < 4; i++) {
                u64 a2 = pack2(As[s][ty * 4 + i][k]);
                fma2(acc2[i][0], a2, b0);
                fma2(acc2[i][1], a2, b1);
            }
        }
    }
#pragma unroll
    for (int i = 0; i < 4; i++) {
        int r = row0 + ty * 4 + i;
        float2 p0 = unpack2(acc2[i][0]), p1 = unpack2(acc2[i][1]);
        float va[4] = {p0.x, p0.y, p1.x, p1.y};
#pragma unroll
        for (int j = 0; j < 4; j++)
            gemm_epi(C, bias, r, col0 + tx * 4 + j, ldc, act, accum, transC, va[j]);
    }
}

// ---------------- generic scalar GEMM (emb / out) ----------------
__global__ __launch_bounds__(256)
void gemm_f32(const float* __restrict__ A, const float* __restrict__ B,
              float* __restrict__ C, const float* __restrict__ bias,
              int M, int Ncol, int K, int lda, int ldb, int ldc,
              int act, int accum)
{
    __shared__ float As[64][36];
    __shared__ float Bs[32][72];
    int tid = threadIdx.x, tx = tid & 15, ty = tid >> 4;
    int row0 = blockIdx.y * 64, col0 = blockIdx.x * 64;
    int nc = (K + 31) >> 5;
    u64 acc2[4][2] = {};

    for (int c = 0; c < nc; c++) {
        __syncthreads();
        for (int i = tid; i < 64 * 32; i += 256) {
            int r = i >> 5, k = i & 31, kg = c * 32 + k;
            As[r][k] = (kg < K) ? A[(size_t)(row0 + r) * lda + kg] : 0.f;
        }
        for (int i = tid; i < 32 * 64; i += 256) {
            int k = i >> 6, cc = i & 63, kg = c * 32 + k;
            float v = 0.f;
            if (kg < K && col0 + cc < Ncol) v = B[(size_t)kg * ldb + col0 + cc];
            Bs[k][cc] = v;
        }
        __syncthreads();
#pragma unroll
        for (int k = 0; k < 32; k++) {
            u64 b0 = *(const u64*)&Bs[k][tx * 4];
            u64 b1 = *(const u64*)&Bs[k][tx * 4 + 2];
#pragma unroll
            for (int i = 0; i < 4; i++) {
                u64 a2 = pack2(As[ty * 4 + i][k]);
                fma2(acc2[i][0], a2, b0);
                fma2(acc2[i][1], a2, b1);
            }
        }
    }
#pragma unroll
    for (int i = 0; i < 4; i++) {
        int r = row0 + ty * 4 + i;
        float2 p0 = unpack2(acc2[i][0]), p1 = unpack2(acc2[i][1]);
        float va[4] = {p0.x, p0.y, p1.x, p1.y};
#pragma unroll
        for (int j = 0; j < 4; j++) {
            int c = col0 + tx * 4 + j;
            if (c < Ncol) gemm_epi(C, bias, r, c, ldc, act, accum, 0, va[j]);
        }
    }
}

// ---------------- 2-pass split-bf16 logits (hh + lo*h), bf16 out ----------------
#define LOG_LD 72
#define LOG_T (128 * LOG_LD * 2)
#define LOG_SMEM (3 * LOG_T)
__global__ __launch_bounds__(256)
void logits_mma_kernel(const float* __restrict__ qk)
{
    extern __shared__ char dsm[];
    unsigned short (*Qhi)[LOG_LD] = (unsigned short(*)[LOG_LD])(dsm);
    unsigned short (*Qlo)[LOG_LD] = (unsigned short(*)[LOG_LD])(dsm + LOG_T);
    unsigned short (*Khi)[LOG_LD] = (unsigned short(*)[LOG_LD])(dsm + 2 * LOG_T);
    int tid = threadIdx.x, lane = tid & 31, wid = tid >> 5;
    int m0 = blockIdx.x * 128, n0 = blockIdx.y * 128, h = blockIdx.z;

    for (int i = tid; i < 128 * 16; i += 256) {
        int r = i >> 4, k4 = (i & 15) * 4;
        float4 v = *(const float4*)&qk[(size_t)(n0 + r) * 512 + h * 64 + k4];
        ushort4 hs, ls;
        hs.x = bfu(v.x); ls.x = bfu(v.x - bff(hs.x));
        hs.y = bfu(v.y); ls.y = bfu(v.y - bff(hs.y));
        hs.z = bfu(v.z); ls.z = bfu(v.z - bff(hs.z));
        hs.w = bfu(v.w); ls.w = bfu(v.w - bff(hs.w));
        *(ushort4*)&Qhi[r][k4] = hs;
        *(ushort4*)&Qlo[r][k4] = ls;
        float4 w = *(const float4*)&qk[(size_t)(m0 + r) * 512 + 256 + h * 64 + k4];
        ushort4 ks;
        ks.x = bfu(w.x); ks.y = bfu(w.y); ks.z = bfu(w.z); ks.w = bfu(w.w);
        *(ushort4*)&Khi[r][k4] = ks;
    }
    __syncthreads();

    int g = lane >> 2, t = lane & 3;
    int wm = (wid >> 2) * 64, wn = (wid & 3) * 32;
    float c[4][4][4] = {};

#pragma unroll
    for (int k0 = 0; k0 < 64; k0 += 16) {
#pragma unroll
        for (int p = 0; p < 2; p++) {
            unsigned short (*A)[LOG_LD] = (p == 1) ? Qlo : Qhi;
            uint32_t a[4][4];
#pragma unroll
            for (int mt = 0; mt < 4; mt++) {
                int r = wm + mt * 16 + g;
                a[mt][0] = *(const uint32_t*)&A[r][k0 + 2 * t];
                a[mt][1] = *(const uint32_t*)&A[r + 8][k0 + 2 * t];
                a[mt][2] = *(const uint32_t*)&A[r][k0 + 2 * t + 8];
                a[mt][3] = *(const uint32_t*)&A[r + 8][k0 + 2 * t + 8];
            }
#pragma unroll
            for (int nt = 0; nt < 4; nt++) {
                int rn = wn + nt * 8 + g;
                uint32_t b[2] = {*(const uint32_t*)&Khi[rn][k0 + 2 * t],
                                 *(const uint32_t*)&Khi[rn][k0 + 2 * t + 8]};
#pragma unroll
                for (int mt = 0; mt < 4; mt++) mma16(c[mt][nt], a[mt], b);
            }
        }
    }
#pragma unroll
    for (int mt = 0; mt < 4; mt++)
#pragma unroll
        for (int nt = 0; nt < 4; nt++) {
            int row = n0 + wm + mt * 16 + g, col = m0 + wn + nt * 8 + 2 * t;
            size_t base = ((size_t)h * Nn + row) * Nn + col;
            uint32_t lo = (uint32_t)bfu(c[mt][nt][0] * 0.125f) | ((uint32_t)bfu(c[mt][nt][1] * 0.125f) << 16);
            uint32_t hi = (uint32_t)bfu(c[mt][nt][2] * 0.125f) | ((uint32_t)bfu(c[mt][nt][3] * 0.125f) << 16);
            *(uint32_t*)&g_attn[base] = lo;
            *(uint32_t*)&g_attn[base + 8 * (size_t)Nn] = hi;
        }
}

// ---------------- bf16 combined agg/mix/agg0 via mma.sync m16n8k16 ----------------
#define NN_LD 40
#define NN_ASZ (128 * NN_LD * 2)
#define NN_STG (2 * NN_ASZ)
#define NN_SMEM (2 * NN_STG)
__global__ __launch_bounds__(256)
void nn_mma_kernel()
{
    extern __shared__ char dsm[];
    int tid = threadIdx.x, lane = tid & 31, wid = tid >> 5;
    int ct = blockIdx.x, n0 = blockIdx.y * 128;

    const bf16* Ap; float* Cp; int NC, vtrow, col0, ldc, acc;
    if (ct < 4)       { NC = 128; Ap = g_ab; vtrow = ct * 128; col0 = ct * 128; Cp = g_agg; ldc = 1088; acc = 0; }
    else if (ct < 7)  { NC = 128; int c = ct - 4; Ap = g_W + (size_t)c * NNsz; vtrow = 800; col0 = 544 + c * 128; Cp = g_agg; ldc = 1088; acc = 0; }
    else if (ct == 7) { NC = 32;  Ap = g_ab; vtrow = 512; col0 = 512; Cp = g_agg; ldc = 1088; acc = 0; }
    else if (ct < 13) { NC = 32;  int c = ct - 8; Ap = g_W + (size_t)(3 + c) * NNsz; vtrow = 928; col0 = 928 + c * 32; Cp = g_agg; ldc = 1088; acc = 0; }
    else              { NC = 64;  int h = ct - 13; Ap = g_attnb + (size_t)h * NNsz; vtrow = 544 + h * 64; col0 = h * 64; Cp = g_x0; ldc = 256; acc = 1; }

    const bf16* Arow = Ap + (size_t)n0 * Nn;
    const bf16* Brow = g_Vt + (size_t)vtrow * Nn;
    int NT = NC / 32;
    int bcpy = NC * 4;

    int g = lane >> 2, t = lane & 3;
    int wm = (wid >> 2) * 64, wn = (wid & 3) * (NC / 4);
    float c[4][4][4] = {};

    const int NCH = Nn / 32;
    {
        unsigned short* As = (unsigned short*)(dsm);
        unsigned short* Bs = (unsigned short*)(dsm + NN_ASZ);
#pragma unroll
        for (int i = 0; i < 2; i++) {
            int idx = tid + i * 256, r = idx >> 2, c8 = (idx & 3) * 8;
            __pipeline_memcpy_async(&As[r * NN_LD + c8], &Arow[(size_t)r * Nn + c8], 16);
        }
#pragma unroll
        for (int i = 0; i < 2; i++) {
            int idx = tid + i * 256;
            if (idx < bcpy) {
                int r = idx >> 2, c8 = (idx & 3) * 8;
                __pipeline_memcpy_async(&Bs[r * NN_LD + c8], &Brow[(size_t)r * Nn + c8], 16);
            }
        }
        __pipeline_commit();
    }
#pragma unroll 1
    for (int ch = 0; ch < NCH; ch++) {
        __pipeline_wait_prior(0);
        __syncthreads();
        if (ch + 1 < NCH) {
            int s = (ch + 1) & 1, kk = (ch + 1) * 32;
            unsigned short* As = (unsigned short*)(dsm + s * NN_STG);
            unsigned short* Bs = (unsigned short*)(dsm + s * NN_STG + NN_ASZ);
#pragma unroll
            for (int i = 0; i < 2; i++) {
                int idx = tid + i * 256, r = idx >> 2, c8 = (idx & 3) * 8;
                __pipeline_memcpy_async(&As[r * NN_LD + c8], &Arow[(size_t)r * Nn + kk + c8], 16);
            }
#pragma unroll
            for (int i = 0; i < 2; i++) {
                int idx = tid + i * 256;
                if (idx < bcpy) {
                    int r = idx >> 2, c8 = (idx & 3) * 8;
                    __pipeline_memcpy_async(&Bs[r * NN_LD + c8], &Brow[(size_t)r * Nn + kk + c8], 16);
                }
            }
            __pipeline_commit();
        }
        const unsigned short* As = (const unsigned short*)(dsm + (ch & 1) * NN_STG);
        const unsigned short* Bs = (const unsigned short*)(dsm + (ch & 1) * NN_STG + NN_ASZ);
#pragma unroll
        for (int k0 = 0; k0 < 32; k0 += 16) {
            uint32_t a[4][4];
#pragma unroll
            for (int mt = 0; mt < 4; mt++) {
                int r = wm + mt * 16 + g;
                a[mt][0] = *(const uint32_t*)&As[r * NN_LD + k0 + 2 * t];
                a[mt][1] = *(const uint32_t*)&As[(r + 8) * NN_LD + k0 + 2 * t];
                a[mt][2] = *(const uint32_t*)&As[r * NN_LD + k0 + 2 * t + 8];
                a[mt][3] = *(const uint32_t*)&As[(r + 8) * NN_LD + k0 + 2 * t + 8];
            }
#pragma unroll
            for (int nt = 0; nt < 4; nt++) {
                if (nt < NT) {
                    int rn = wn + nt * 8 + g;
                    uint32_t b[2] = {*(const uint32_t*)&Bs[rn * NN_LD + k0 + 2 * t],
                                     *(const uint32_t*)&Bs[rn * NN_LD + k0 + 2 * t + 8]};
#pragma unroll
                    for (int mt = 0; mt < 4; mt++) mma16(c[mt][nt], a[mt], b);
                }
            }
        }
    }
#pragma unroll
    for (int mt = 0; mt < 4; mt++)
#pragma unroll
        for (int nt = 0; nt < 4; nt++) {
            if (nt < NT) {
                int row = n0 + wm + mt * 16 + g, col = col0 + wn + nt * 8 + 2 * t;
                size_t i0 = (size_t)row * ldc + col, i1 = (size_t)(row + 8) * ldc + col;
                if (acc) {
                    float2 o0 = *(float2*)&Cp[i0], o1 = *(float2*)&Cp[i1];
                    *(float2*)&Cp[i0] = make_float2(o0.x + c[mt][nt][0], o0.y + c[mt][nt][1]);
                    *(float2*)&Cp[i1] = make_float2(o1.x + c[mt][nt][2], o1.y + c[mt][nt][3]);
                } else {
                    *(float2*)&Cp[i0] = make_float2(c[mt][nt][0], c[mt][nt][1]);
                    *(float2*)&Cp[i1] = make_float2(c[mt][nt][2], c[mt][nt][3]);
                }
            }
        }
}

// ---------------- maxless softmax + fused build_w ----------------
__global__ __launch_bounds__(256)
void softmax_kernel(const float* __restrict__ pos)
{
    int n = blockIdx.x;
    __shared__ float row[Nn];
    __shared__ float accr[Nn];
    __shared__ float red[256];
    int tid = threadIdx.x;
    for (int i = tid * 4; i < Nn; i += 1024) *(float4*)&accr[i] = make_float4(0.f, 0.f, 0.f, 0.f);

    for (int h = 0; h < 4; h++) {
        const bf16* p = g_attn + ((size_t)h * Nn + n) * Nn;
        bf16* pb = g_attnb + ((size_t)h * Nn + n) * Nn;
        __syncthreads();
        float sum = 0.f;
        for (int i = tid * 4; i < Nn; i += 1024) {
            ushort4 u = *(const ushort4*)&p[i];
            float4 e = make_float4(__expf(bff(u.x)), __expf(bff(u.y)), __expf(bff(u.z)), __expf(bff(u.w)));
            *(float4*)&row[i] = e;
            sum += e.x + e.y + e.z + e.w;
        }
        red[tid] = sum; __syncthreads();
        for (int s = 128; s > 0; s >>= 1) { if (tid < s) red[tid] += red[tid + s]; __syncthreads(); }
        float inv = 1.f / red[0]; __syncthreads();
        for (int i = tid * 4; i < Nn; i += 1024) {
            float4 v = *(float4*)&row[i];
            float4 e = make_float4(v.x * inv, v.y * inv, v.z * inv, v.w * inv);
            ushort4 eb;
            eb.x = bfu(e.x); eb.y = bfu(e.y); eb.z = bfu(e.z); eb.w = bfu(e.w);
            *(ushort4*)&pb[i] = eb;
            float4 a = *(float4*)&accr[i];
            *(float4*)&accr[i] = make_float4(a.x + e.x, a.y + e.y, a.z + e.z, a.w + e.w);
        }
    }
    __syncthreads();
    float pnx = pos[n * 3 + 0], pny = pos[n * 3 + 1], pnz = pos[n * 3 + 2];
    for (int i = tid * 4; i < Nn; i += 1024) {
        float4 a4 = *(float4*)&accr[i];
        float av[4] = {a4.x * 0.25f, a4.y * 0.25f, a4.z * 0.25f, a4.w * 0.25f};
        ushort4 qb;
        qb.x = bfu(av[0]); qb.y = bfu(av[1]); qb.z = bfu(av[2]); qb.w = bfu(av[3]);
        *(ushort4*)&g_ab[(size_t)n * Nn + i] = qb;
        unsigned short o[8][4];
#pragma unroll
        for (int tt = 0; tt < 4; tt++) {
            int m = i + tt;
            float a = av[tt];
            float rx = pos[m * 3 + 0] - pnx;
            float ry = pos[m * 3 + 1] - pny;
            float rz = pos[m * 3 + 2] - pnz;
            float r2 = rx * rx + ry * ry + rz * rz;
            bool ok = r2 > 1e-12f;
            float inv = ok ? rsqrtf(r2) : 0.f;
            float valid = ok ? 1.f : 0.f;
            float ux = rx * inv, uy = ry * inv, uz = rz * inv;
            o[0][tt] = bfu(a * ux); o[1][tt] = bfu(a * uy); o[2][tt] = bfu(a * uz);
            o[3][tt] = bfu(a * (SQRT3 * ux * uy));
            o[4][tt] = bfu(a * (SQRT3 * uy * uz));
            o[5][tt] = bfu(a * (0.5f * (3.f * uz * uz - 1.f)) * valid);
            o[6][tt] = bfu(a * (SQRT3 * ux * uz));
            o[7][tt] = bfu(a * (0.5f * SQRT3 * (ux * ux - uy * uy)));
        }
#pragma unroll
        for (int cc = 0; cc < 8; cc++)
            *(ushort4*)&g_W[cc * NNsz + (size_t)n * Nn + i] = make_ushort4(o[cc][0], o[cc][1], o[cc][2], o[cc][3]);
    }
}

// ---------------- invariants ----------------
__global__ void invariants_kernel()
{
    const int total = Nn * Ff;
    for (int i = blockIdx.x * blockDim.x + threadIdx.x; i < total; i += gridDim.x * blockDim.x) {
        int n = i / Ff, c = i % Ff;
        float v;
        if (c < D0) v = g_x0[n * D0 + c];
        else if (c < D0 + D1) {
            const float* p = &g_x1[(n * D1 + (c - D0)) * 3];
            v = sqrtf(p[0] * p[0] + p[1] * p[1] + p[2] * p[2]);
        } else {
            const float* p = &g_x2[(n * D2 + (c - D0 - D1)) * 5];
            v = sqrtf(p[0] * p[0] + p[1] * p[1] + p[2] * p[2] + p[3] * p[3] + p[4] * p[4]);
        }
        g_inv[i] = v;
    }
}

// ---------------- v1/v2 channel mixes ----------------
__global__ __launch_bounds__(128)
void v1_kernel(const float* __restrict__ Wv1)
{
    int m = blockIdx.x;
    __shared__ float sx[D1 * 3];
    int tid = threadIdx.x;
    for (int i = tid; i < D1 * 3; i += 128) sx[i] = g_x1[m * D1 * 3 + i];
    __syncthreads();
    float a0 = 0.f, a1 = 0.f, a2 = 0.f;
#pragma unroll 8
    for (int d = 0; d < D1; d++) {
        float w = Wv1[d * D1 + tid];
        a0 += sx[d * 3 + 0] * w;
        a1 += sx[d * 3 + 1] * w;
        a2 += sx[d * 3 + 2] * w;
    }
    g_Vt[(size_t)(tid * 3 + 0) * Nn + m] = __float2bfloat16_rn(a0);
    g_Vt[(size_t)(tid * 3 + 1) * Nn + m] = __float2bfloat16_rn(a1);
    g_Vt[(size_t)(tid * 3 + 2) * Nn + m] = __float2bfloat16_rn(a2);
}

__global__ __launch_bounds__(32)
void v2_kernel(const float* __restrict__ Wv2)
{
    int m = blockIdx.x;
    __shared__ float sx[D2 * 5];
    int tid = threadIdx.x;
    for (int i = tid; i < D2 * 5; i += 32) sx[i] = g_x2[m * D2 * 5 + i];
    __syncthreads();
    float a[5] = {};
#pragma unroll 8
    for (int d = 0; d < D2; d++) {
        float w = Wv2[d * D2 + tid];
#pragma unroll
        for (int c = 0; c < 5; c++) a[c] += sx[d * 5 + c] * w;
    }
#pragma unroll
    for (int c = 0; c < 5; c++) g_Vt[(size_t)(384 + tid * 5 + c) * Nn + m] = __float2bfloat16_rn(a[c]);
}

// ---------------- finalize ----------------
__global__ void finalize_kernel()
{
    const int total = Nn * 544;
    for (int i = blockIdx.x * blockDim.x + threadIdx.x; i < total; i += gridDim.x * blockDim.x) {
        int n = i / 544, t = i % 544;
        if (t < 384) {
            int d = t / 3, c = t % 3;
            g_x1[n * 384 + t] += g_agg[(size_t)n * 1088 + t] + g_agg[(size_t)n * 1088 + 544 + c * 128 + d];
        } else {
            int tt = t - 384, e = tt / 5, c = tt % 5;
            g_x2[n * 160 + tt] += g_agg[(size_t)n * 1088 + 384 + tt] + g_agg[(size_t)n * 1088 + 928 + c * 32 + e];
        }
    }
}

// ---------------- gate + fold into g_inv ----------------
__global__ void gate_inv_kernel()
{
    const int total = Nn * 704;
    for (int i = blockIdx.x * blockDim.x + threadIdx.x; i < total; i += gridDim.x * blockDim.x) {
        int n = i / 704, t = i % 704;
        if (t < 384) g_x1[n * 384 + t] *= g_gate[n * 160 + t / 3];
        else if (t < 544) { int tt = t - 384; g_x2[n * 160 + tt] *= g_gate[n * 160 + 128 + tt / 5]; }
        else { int d = t - 544; g_inv[n * Ff + 256 + d] *= g_gate[n * 160 + d]; }
    }
}

__global__ void zero_kernel()
{
    const int t1 = Nn * 384, total = Nn * 384 + Nn * 160;
    for (int i = blockIdx.x * blockDim.x + threadIdx.x; i < total; i += gridDim.x * blockDim.x) {
        if (i < t1) g_x1[i] = 0.f; else g_x2[i - t1] = 0.f;
    }
}

// ---------------- host ----------------
extern "C" void kernel_launch(void* const* d_in, const int* in_sizes, int n_in,
                              void* d_out, int out_size)
{
    const float* x     = (const float*)d_in[0];
    const float* pos   = (const float*)d_in[1];
    const float* emb_W = (const float*)d_in[2];
    const float* emb_b = (const float*)d_in[3];
    const float* Wq    = (const float*)d_in[4];
    const float* Wk    = (const float*)d_in[5];
    const float* Wv0   = (const float*)d_in[6];
    const float* Wv1   = (const float*)d_in[7];
    const float* Wv2   = (const float*)d_in[8];
    const float* Ws1   = (const float*)d_in[9];
    const float* Ws2   = (const float*)d_in[10];
    const float* Wffa  = (const float*)d_in[11];
    const float* Wffb  = (const float*)d_in[12];
    const float* Wg    = (const float*)d_in[13];
    const float* out_W = (const float*)d_in[14];
    const float* out_b = (const float*)d_in[15];
    float* out = (float*)d_out;

    static cudaStream_t sB = nullptr;
    static cudaEvent_t evB, evN, evF0, evFin, evL;
    if (!sB) {
        cudaFuncSetAttribute(logits_mma_kernel, cudaFuncAttributeMaxDynamicSharedMemorySize, LOG_SMEM);
        cudaFuncSetAttribute(nn_mma_kernel, cudaFuncAttributeMaxDynamicSharedMemorySize, NN_SMEM);
        cudaStreamCreateWithFlags(&sB, cudaStreamNonBlocking);
        cudaEventCreateWithFlags(&evB,   cudaEventDisableTiming);
        cudaEventCreateWithFlags(&evN,   cudaEventDisableTiming);
        cudaEventCreateWithFlags(&evF0,  cudaEventDisableTiming);
        cudaEventCreateWithFlags(&evFin, cudaEventDisableTiming);
        cudaEventCreateWithFlags(&evL,   cudaEventDisableTiming);
    }

    void* vp;
    cudaGetSymbolAddress(&vp, g_x0);     float* px0   = (float*)vp;
    cudaGetSymbolAddress(&vp, g_inv);    float* pinv  = (float*)vp;
    cudaGetSymbolAddress(&vp, g_qk);     float* pqk   = (float*)vp;
    cudaGetSymbolAddress(&vp, g_Vt);     bf16*  pVt   = (bf16*)vp;
    cudaGetSymbolAddress(&vp, g_ff);     float* pff   = (float*)vp;
    cudaGetSymbolAddress(&vp, g_gate);   float* pgate = (float*)vp;
    cudaGetSymbolAddress(&vp, g_qkpack); float* pqkp  = (float*)vp;
    cudaGetSymbolAddress(&vp, g_vpack);  float* pvp   = (float*)vp;
    cudaGetSymbolAddress(&vp, g_gpack);  float* pgp   = (float*)vp;
    cudaGetSymbolAddress(&vp, g_opack);  float* pop   = (float*)vp;

    pack_kernel<<<2048, 256>>>(Wq, Wk, Wv0, Ws1, Ws2, Wg, out_W);
    zero_kernel<<<512, 256>>>();
    gemm_f32<<<dim3(4, 32), 256>>>(x, emb_W, px0, emb_b, Nn, D0, 118, 118, D0, D0, 0, 0);
    invariants_kernel<<<1024, 256>>>();
    cudaEventRecord(evF0, 0);   // x0 ready
    cudaEventRecord(evL, 0);    // x1/x2 + g_inv ready

    for (int l = 0; l < NL; l++) {
        const float* qk_l   = pqkp + (size_t)l * 416 * 512;
        const float* vp_l   = pvp  + (size_t)l * 256 * 448;
        const float* gp_l   = pgp  + (size_t)l * 416 * 192;
        const float* Wv1_l  = Wv1  + (size_t)l * D1 * D1;
        const float* Wv2_l  = Wv2  + (size_t)l * D2 * D2;
        const float* Wffa_l = Wffa + (size_t)l * D0 * 512;
        const float* Wffb_l = Wffb + (size_t)l * 512 * D0;

        // ---- B-chain on sB: builds g_Vt (needs x0 after prev ffb, x1/x2 after prev gate_inv)
        cudaStreamWaitEvent(sB, evF0, 0);
        gemm_bn32<<<dim3(13, 32), 128, 0, sB>>>(px0, vp_l, (float*)(pVt + (size_t)544 * Nn), nullptr,
                                                D0, D0, 448, Nn, 0, 0, 1);
        cudaStreamWaitEvent(sB, evL, 0);
        v1_kernel<<<Nn, 128, 0, sB>>>(Wv1_l);
        v2_kernel<<<Nn, 32, 0, sB>>>(Wv2_l);
        cudaEventRecord(evB, sB);

        // ---- A-chain on default stream
        gemm_bn32<<<dim3(16, 32), 128>>>(pinv, qk_l, pqk, nullptr, Ff, Ff, 512, 512, 0, 0, 0);
        logits_mma_kernel<<<dim3(16, 16, 4), 256, LOG_SMEM>>>(pqk);
        softmax_kernel<<<Nn, 256>>>(pos);

        cudaStreamWaitEvent(0, evB, 0);
        nn_mma_kernel<<<dim3(17, 16), 256, NN_SMEM>>>();
        cudaEventRecord(evN, 0);

        // ff chain (x0) on default; finalize (x1/x2) concurrently on sB
        gemm_bn32<<<dim3(16, 32), 128>>>(px0, Wffa_l, pff, nullptr, D0, D0, 512, 512, 1, 0, 0);
        gemm_bn32<<<dim3(8, 32), 128>>>(pff, Wffb_l, px0, nullptr, 512, 512, D0, D0, 0, 1, 0);
        cudaEventRecord(evF0, 0);

        cudaStreamWaitEvent(sB, evN, 0);
        finalize_kernel<<<1024, 256, 0, sB>>>();
        cudaEventRecord(evFin, sB);

        cudaStreamWaitEvent(0, evFin, 0);
        invariants_kernel<<<1024, 256>>>();
        gemm_bn32<<<dim3(5, 32), 128>>>(pinv, gp_l, pgate, nullptr, Ff, Ff, 192, 160, 2, 0, 0);
        gate_inv_kernel<<<1024, 256>>>();
        cudaEventRecord(evL, 0);
    }
    gemm_f32<<<dim3(1, 32), 256>>>(px0, pop, out, out_b, Nn, NCLS, D0, D0, 64, NCLS, 0, 0);
}